// round 3
// baseline (speedup 1.0000x reference)
#include <cuda_runtime.h>
#include <math.h>

#define BATCH  4
#define SEQ    2048
#define DMODEL 1024
#define DK     64

// Scratch for projected Q/K/V: [3][B*N*DK] floats = 6 MB
__device__ float g_proj[3][BATCH * SEQ * DK];

// XOR-swizzled [64][64] float tile addressing (float4-granular swizzle).
// phys index for (row, col): row*64 + ((col>>2 ^ (row>>2 & 15))<<2) + (col&3)
__device__ __forceinline__ int sw_idx(int row, int col) {
    return row * 64 + ((((col >> 2) ^ ((row >> 2) & 15)) << 2) | (col & 3));
}
// float4-aligned variant: col4 in [0,16)
__device__ __forceinline__ int sw_idx4(int row, int col4) {
    return row * 64 + ((col4 ^ ((row >> 2) & 15)) << 2);
}

// ---------------------------------------------------------------------------
// Projection GEMM: Y = X[8192,1024] @ W[1024,64] + b
// grid (128, 1, 3)  z selects q/k/v; 256 threads; BM=64, BK=16
// each thread computes a 4x4 micro-tile
// ---------------------------------------------------------------------------
__global__ __launch_bounds__(256) void proj_kernel(
    const float* __restrict__ x0, const float* __restrict__ x1, const float* __restrict__ x2,
    const float* __restrict__ w0, const float* __restrict__ w1, const float* __restrict__ w2,
    const float* __restrict__ b0, const float* __restrict__ b1, const float* __restrict__ b2)
{
    __shared__ float As[16][68];  // [k][row] transposed (padded)
    __shared__ float Ws[16][64];  // [k][col]

    const int sel = blockIdx.z;
    const float* __restrict__ X = (sel == 0) ? x0 : (sel == 1) ? x1 : x2;
    const float* __restrict__ W = (sel == 0) ? w0 : (sel == 1) ? w1 : w2;
    const float* __restrict__ Bb = (sel == 0) ? b0 : (sel == 1) ? b1 : b2;
    float* __restrict__ Y = g_proj[sel];

    const int tid = threadIdx.x;
    const int ty = tid >> 4, tx = tid & 15;
    const int rowBase = blockIdx.x * 64;

    const int arow = tid >> 2, ac4 = tid & 3;     // A tile: 64x16 = 256 float4
    const int wrow = tid >> 4, wc4 = tid & 15;    // W tile: 16x64 = 256 float4

    float acc[4][4] = {};

    for (int k0 = 0; k0 < DMODEL; k0 += 16) {
        float4 a = *(const float4*)(X + (size_t)(rowBase + arow) * DMODEL + k0 + ac4 * 4);
        As[ac4 * 4 + 0][arow] = a.x;
        As[ac4 * 4 + 1][arow] = a.y;
        As[ac4 * 4 + 2][arow] = a.z;
        As[ac4 * 4 + 3][arow] = a.w;
        *(float4*)&Ws[wrow][wc4 * 4] = *(const float4*)(W + (size_t)(k0 + wrow) * DK + wc4 * 4);
        __syncthreads();
#pragma unroll
        for (int k = 0; k < 16; ++k) {
            float av[4], wv[4];
            *(float4*)av = *(const float4*)&As[k][ty * 4];
            *(float4*)wv = *(const float4*)&Ws[k][tx * 4];
#pragma unroll
            for (int i = 0; i < 4; ++i)
#pragma unroll
                for (int j = 0; j < 4; ++j)
                    acc[i][j] = fmaf(av[i], wv[j], acc[i][j]);
        }
        __syncthreads();
    }

    float bj[4];
    *(float4*)bj = *(const float4*)(Bb + tx * 4);
#pragma unroll
    for (int i = 0; i < 4; ++i) {
        float4 o;
        o.x = acc[i][0] + bj[0];
        o.y = acc[i][1] + bj[1];
        o.z = acc[i][2] + bj[2];
        o.w = acc[i][3] + bj[3];
        *(float4*)(Y + (size_t)(rowBase + ty * 4 + i) * DK + tx * 4) = o;
    }
}

// ---------------------------------------------------------------------------
// Fused attention: out = softmax_unstab(Qp Kp^T / 8) Vp
// grid (SEQ/64, BATCH); 256 threads. 64 query rows per block; loop 64-key tiles.
// Static smem, 48KB total, XOR-swizzled tiles:
//   Qs  : Q^T  [d][r], pre-scaled 1/8
//   KEs : K^T  [d][c], reused as E^T [c][r] after S is computed
//   Vs  : V    [c][d]
// ---------------------------------------------------------------------------
__global__ __launch_bounds__(256) void attn_kernel(float* __restrict__ out)
{
    __shared__ float Qs[64 * 64];
    __shared__ float KEs[64 * 64];
    __shared__ float Vs[64 * 64];

    const int tid = threadIdx.x;
    const int ty = tid >> 4, tx = tid & 15;
    const int b  = blockIdx.y;
    const int q0 = blockIdx.x * 64;

    const float* __restrict__ Qg = g_proj[0] + ((size_t)b * SEQ + q0) * DK;
    const float* __restrict__ Kg = g_proj[1] + (size_t)b * SEQ * DK;
    const float* __restrict__ Vg = g_proj[2] + (size_t)b * SEQ * DK;

    // Load Q tile transposed into smem, folding in the 1/sqrt(dk) = 0.125 scale
#pragma unroll
    for (int p = 0; p < 4; ++p) {
        int f = p * 256 + tid;
        int r = f >> 4, c4 = f & 15;
        float4 q = *(const float4*)(Qg + (size_t)r * DK + c4 * 4);
        Qs[sw_idx(c4 * 4 + 0, r)] = q.x * 0.125f;
        Qs[sw_idx(c4 * 4 + 1, r)] = q.y * 0.125f;
        Qs[sw_idx(c4 * 4 + 2, r)] = q.z * 0.125f;
        Qs[sw_idx(c4 * 4 + 3, r)] = q.w * 0.125f;
    }

    float oacc[4][4] = {};
    float den[4] = {};
    __syncthreads();

    for (int n0 = 0; n0 < SEQ; n0 += 64) {
        // Load K tile (transposed) and V tile (direct, swizzled rows)
#pragma unroll
        for (int p = 0; p < 4; ++p) {
            int f = p * 256 + tid;
            int r = f >> 4, c4 = f & 15;
            float4 kv = *(const float4*)(Kg + (size_t)(n0 + r) * DK + c4 * 4);
            KEs[sw_idx(c4 * 4 + 0, r)] = kv.x;
            KEs[sw_idx(c4 * 4 + 1, r)] = kv.y;
            KEs[sw_idx(c4 * 4 + 2, r)] = kv.z;
            KEs[sw_idx(c4 * 4 + 3, r)] = kv.w;
            float4 vv = *(const float4*)(Vg + (size_t)(n0 + r) * DK + c4 * 4);
            *(float4*)&Vs[sw_idx4(r, c4)] = vv;
        }
        __syncthreads();

        // S = (Q/8) K^T : each thread 4 rows x 4 cols
        float s[4][4] = {};
#pragma unroll 8
        for (int d = 0; d < 64; ++d) {
            float qv[4], kv[4];
            *(float4*)qv = *(const float4*)&Qs[sw_idx4(d, ty)];
            *(float4*)kv = *(const float4*)&KEs[sw_idx4(d, tx)];
#pragma unroll
            for (int i = 0; i < 4; ++i)
#pragma unroll
                for (int j = 0; j < 4; ++j)
                    s[i][j] = fmaf(qv[i], kv[j], s[i][j]);
        }
        __syncthreads();  // everyone done reading K before overwriting with E^T

        // exp + row-sum (partial over this thread's 4 cols, reduce across 16 tx lanes)
        float rs[4];
#pragma unroll
        for (int i = 0; i < 4; ++i) {
            float e0 = __expf(s[i][0]);
            float e1 = __expf(s[i][1]);
            float e2 = __expf(s[i][2]);
            float e3 = __expf(s[i][3]);
            s[i][0] = e0; s[i][1] = e1; s[i][2] = e2; s[i][3] = e3;
            rs[i] = (e0 + e1) + (e2 + e3);
        }
#pragma unroll
        for (int m = 1; m < 16; m <<= 1) {
#pragma unroll
            for (int i = 0; i < 4; ++i)
                rs[i] += __shfl_xor_sync(0xffffffffu, rs[i], m);
        }
#pragma unroll
        for (int i = 0; i < 4; ++i) den[i] += rs[i];

        // Store E^T into the (now dead) K buffer: E^T[c][r]
#pragma unroll
        for (int i = 0; i < 4; ++i)
#pragma unroll
            for (int j = 0; j < 4; ++j)
                KEs[sw_idx(tx * 4 + j, ty * 4 + i)] = s[i][j];
        __syncthreads();

        // O += E^T' * V : thread owns 4 rows x 4 dims
#pragma unroll 8
        for (int c = 0; c < 64; ++c) {
            float ev[4], vv[4];
            *(float4*)ev = *(const float4*)&KEs[sw_idx4(c, ty)];
            *(float4*)vv = *(const float4*)&Vs[sw_idx4(c, tx)];
#pragma unroll
            for (int i = 0; i < 4; ++i)
#pragma unroll
                for (int j = 0; j < 4; ++j)
                    oacc[i][j] = fmaf(ev[i], vv[j], oacc[i][j]);
        }
        __syncthreads();  // done with KEs/Vs before next tile load
    }

    // Normalize and write out [B, N, DK]
    float* __restrict__ Og = out + ((size_t)b * SEQ + q0) * DK;
#pragma unroll
    for (int i = 0; i < 4; ++i) {
        float inv = 1.0f / den[i];
        float4 o;
        o.x = oacc[i][0] * inv;
        o.y = oacc[i][1] * inv;
        o.z = oacc[i][2] * inv;
        o.w = oacc[i][3] * inv;
        *(float4*)(Og + (size_t)(ty * 4 + i) * DK + tx * 4) = o;
    }
}

// ---------------------------------------------------------------------------
extern "C" void kernel_launch(void* const* d_in, const int* in_sizes, int n_in,
                              void* d_out, int out_size)
{
    const float* q  = (const float*)d_in[0];
    const float* k  = (const float*)d_in[1];
    const float* v  = (const float*)d_in[2];
    const float* Wq = (const float*)d_in[3];
    const float* bq = (const float*)d_in[4];
    const float* Wk = (const float*)d_in[5];
    const float* bk = (const float*)d_in[6];
    const float* Wv = (const float*)d_in[7];
    const float* bv = (const float*)d_in[8];
    float* out = (float*)d_out;

    dim3 pgrid(BATCH * SEQ / 64, 1, 3);
    proj_kernel<<<pgrid, 256>>>(q, k, v, Wq, Wk, Wv, bq, bk, bv);

    dim3 agrid(SEQ / 64, BATCH);
    attn_kernel<<<agrid, 256>>>(out);
}

// round 4
// speedup vs baseline: 2.1498x; 2.1498x over previous
#include <cuda_runtime.h>
#include <math.h>

#define BATCH  4
#define SEQ    2048
#define DMODEL 1024
#define DK     64

// Scratch for projected Q/K/V: [3][B*N*DK] floats = 6 MB
__device__ float g_proj[3][BATCH * SEQ * DK];

// ---- helpers ---------------------------------------------------------------
__device__ __forceinline__ unsigned f2tf(float x) {
    unsigned u;
    asm("cvt.rna.tf32.f32 %0, %1;" : "=r"(u) : "f"(x));
    return u;
}

// D += A(16x8,row) * B(8x8,col)  tf32 inputs, f32 accumulate
__device__ __forceinline__ void mma8(float4& d,
                                     unsigned a0, unsigned a1, unsigned a2, unsigned a3,
                                     unsigned b0, unsigned b1) {
    asm("mma.sync.aligned.m16n8k8.row.col.f32.tf32.tf32.f32 "
        "{%0,%1,%2,%3},{%4,%5,%6,%7},{%8,%9},{%0,%1,%2,%3};"
        : "+f"(d.x), "+f"(d.y), "+f"(d.z), "+f"(d.w)
        : "r"(a0), "r"(a1), "r"(a2), "r"(a3), "r"(b0), "r"(b1));
}

// ---------------------------------------------------------------------------
// Projection: Y = X[8192,1024] @ W[1024,64] + b   (tf32 MMA)
// grid (64,1,3), 256 thr. CTA tile 128 rows x 64 cols; warp = 16 rows x 64 cols.
// K chunks of 32.
// ---------------------------------------------------------------------------
#define PXS 36   // Xs row stride (words)
#define PWS 68   // Wk row stride (words)

__global__ __launch_bounds__(256) void proj_kernel(
    const float* __restrict__ x0, const float* __restrict__ x1, const float* __restrict__ x2,
    const float* __restrict__ w0, const float* __restrict__ w1, const float* __restrict__ w2,
    const float* __restrict__ b0v, const float* __restrict__ b1v, const float* __restrict__ b2v)
{
    __shared__ unsigned Xs[128 * PXS];   // 18432 B
    __shared__ unsigned Wk[32 * PWS];    // 8704 B

    const int sel = blockIdx.z;
    const float* __restrict__ X  = (sel == 0) ? x0 : (sel == 1) ? x1 : x2;
    const float* __restrict__ W  = (sel == 0) ? w0 : (sel == 1) ? w1 : w2;
    const float* __restrict__ Bb = (sel == 0) ? b0v : (sel == 1) ? b1v : b2v;
    float* __restrict__ Y = g_proj[sel];

    const int tid  = threadIdx.x;
    const int wid  = tid >> 5;
    const int lane = tid & 31;
    const int g    = lane >> 2;   // group (row within m16)
    const int m    = lane & 3;    // thread-in-group (k col)
    const int row0 = blockIdx.x * 128;

    float4 acc[8];
#pragma unroll
    for (int n = 0; n < 8; ++n) acc[n] = make_float4(0.f, 0.f, 0.f, 0.f);

    for (int k0 = 0; k0 < DMODEL; k0 += 32) {
        // X tile 128x32 -> Xs (tf32)
#pragma unroll
        for (int p = 0; p < 4; ++p) {
            int f = p * 256 + tid;
            int r = f >> 3, c4 = f & 7;
            float4 xv = *(const float4*)(X + (size_t)(row0 + r) * DMODEL + k0 + c4 * 4);
            uint4 u = make_uint4(f2tf(xv.x), f2tf(xv.y), f2tf(xv.z), f2tf(xv.w));
            *(uint4*)&Xs[r * PXS + c4 * 4] = u;
        }
        // W tile 32x64 -> Wk (tf32)
#pragma unroll
        for (int p = 0; p < 2; ++p) {
            int f = p * 256 + tid;
            int r = f >> 4, c4 = f & 15;
            float4 wv = *(const float4*)(W + (size_t)(k0 + r) * DK + c4 * 4);
            uint4 u = make_uint4(f2tf(wv.x), f2tf(wv.y), f2tf(wv.z), f2tf(wv.w));
            *(uint4*)&Wk[r * PWS + c4 * 4] = u;
        }
        __syncthreads();

#pragma unroll
        for (int kk = 0; kk < 4; ++kk) {
            int r = 16 * wid + g;
            unsigned a0 = Xs[r * PXS + kk * 8 + m];
            unsigned a1 = Xs[(r + 8) * PXS + kk * 8 + m];
            unsigned a2 = Xs[r * PXS + kk * 8 + m + 4];
            unsigned a3 = Xs[(r + 8) * PXS + kk * 8 + m + 4];
#pragma unroll
            for (int n = 0; n < 8; ++n) {
                unsigned bb0 = Wk[(kk * 8 + m) * PWS + n * 8 + g];
                unsigned bb1 = Wk[(kk * 8 + m + 4) * PWS + n * 8 + g];
                mma8(acc[n], a0, a1, a2, a3, bb0, bb1);
            }
        }
        __syncthreads();
    }

    // epilogue: bias + store
#pragma unroll
    for (int n = 0; n < 8; ++n) {
        int col = n * 8 + 2 * m;
        float bj0 = Bb[col], bj1 = Bb[col + 1];
        int r = row0 + 16 * wid + g;
        float2 o0 = make_float2(acc[n].x + bj0, acc[n].y + bj1);
        float2 o1 = make_float2(acc[n].z + bj0, acc[n].w + bj1);
        *(float2*)(Y + (size_t)r * DK + col)       = o0;
        *(float2*)(Y + (size_t)(r + 8) * DK + col) = o1;
    }
}

// ---------------------------------------------------------------------------
// Fused attention with tf32 MMA.
// grid (32, 4), 256 thr (8 warps). CTA: 64 q rows; loop over 64-key tiles.
// Warp (wr=wid&3, wc=wid>>2): S tile rows 16*wr x keys 32*wc..+31.
// O partial per warp: 16 rows x 64 dims over its key half; reduced at end.
// ---------------------------------------------------------------------------
#define AS 68   // Ks/Vs row stride (words)

__global__ __launch_bounds__(256) void attn_kernel(float* __restrict__ out)
{
    __shared__ unsigned Ks[64 * AS];   // 17408 B  (also overlaid by Ofull at end)
    __shared__ unsigned Vs[64 * AS];   // 17408 B
    __shared__ float    den[64];

    float* Ofull = (float*)Ks;         // 64*64*4 = 16384 B <= 17408

    const int tid  = threadIdx.x;
    const int wid  = tid >> 5;
    const int lane = tid & 31;
    const int g    = lane >> 2;
    const int m    = lane & 3;
    const int wr   = wid & 3;
    const int wc   = wid >> 2;

    const int b  = blockIdx.y;
    const int q0 = blockIdx.x * 64;

    const float* __restrict__ Qg = g_proj[0] + ((size_t)b * SEQ + q0) * DK;
    const float* __restrict__ Kg = g_proj[1] + (size_t)b * SEQ * DK;
    const float* __restrict__ Vg = g_proj[2] + (size_t)b * SEQ * DK;

    // ---- stage Q tile through Ks, pull A-fragments into registers ----------
#pragma unroll
    for (int p = 0; p < 4; ++p) {
        int f = p * 256 + tid;
        int r = f >> 4, c4 = f & 15;
        float4 qv = *(const float4*)(Qg + (size_t)r * DK + c4 * 4);
        uint4 u = make_uint4(f2tf(qv.x * 0.125f), f2tf(qv.y * 0.125f),
                             f2tf(qv.z * 0.125f), f2tf(qv.w * 0.125f));
        *(uint4*)&Ks[r * AS + c4 * 4] = u;
    }
    __syncthreads();

    unsigned qa[8][4];
#pragma unroll
    for (int kk = 0; kk < 8; ++kk) {
        int r = 16 * wr + g;
        qa[kk][0] = Ks[r * AS + kk * 8 + m];
        qa[kk][1] = Ks[(r + 8) * AS + kk * 8 + m];
        qa[kk][2] = Ks[r * AS + kk * 8 + m + 4];
        qa[kk][3] = Ks[(r + 8) * AS + kk * 8 + m + 4];
    }
    __syncthreads();   // Ks free for K tiles

    float4 oacc[8];
#pragma unroll
    for (int n = 0; n < 8; ++n) oacc[n] = make_float4(0.f, 0.f, 0.f, 0.f);
    float dp0 = 0.f, dp1 = 0.f;

    const int s0  = (lane & ~3) | (m >> 1);
    const int s1  = s0 + 2;
    const bool od = (m & 1);

    for (int n0 = 0; n0 < SEQ; n0 += 64) {
        // ---- load K & V tiles (tf32) ---------------------------------------
#pragma unroll
        for (int p = 0; p < 4; ++p) {
            int f = p * 256 + tid;
            int r = f >> 4, c4 = f & 15;
            float4 kv = *(const float4*)(Kg + (size_t)(n0 + r) * DK + c4 * 4);
            *(uint4*)&Ks[r * AS + c4 * 4] =
                make_uint4(f2tf(kv.x), f2tf(kv.y), f2tf(kv.z), f2tf(kv.w));
            float4 vv = *(const float4*)(Vg + (size_t)(n0 + r) * DK + c4 * 4);
            *(uint4*)&Vs[r * AS + c4 * 4] =
                make_uint4(f2tf(vv.x), f2tf(vv.y), f2tf(vv.z), f2tf(vv.w));
        }
        __syncthreads();

        // ---- S = Q K^T  (warp: 16 rows x 32 keys) --------------------------
        float4 sa[4];
#pragma unroll
        for (int n = 0; n < 4; ++n) sa[n] = make_float4(0.f, 0.f, 0.f, 0.f);
#pragma unroll
        for (int kk = 0; kk < 8; ++kk) {
#pragma unroll
            for (int n = 0; n < 4; ++n) {
                int krow = 32 * wc + n * 8 + g;
                unsigned bb0 = Ks[krow * AS + kk * 8 + m];
                unsigned bb1 = Ks[krow * AS + kk * 8 + m + 4];
                mma8(sa[n], qa[kk][0], qa[kk][1], qa[kk][2], qa[kk][3], bb0, bb1);
            }
        }

        // ---- exp (tf32-rounded; den uses the SAME rounded values) ----------
#pragma unroll
        for (int n = 0; n < 4; ++n) {
            float e0 = __uint_as_float(f2tf(__expf(sa[n].x)));
            float e1 = __uint_as_float(f2tf(__expf(sa[n].y)));
            float e2 = __uint_as_float(f2tf(__expf(sa[n].z)));
            float e3 = __uint_as_float(f2tf(__expf(sa[n].w)));
            dp0 += e0 + e1;
            dp1 += e2 + e3;
            sa[n] = make_float4(e0, e1, e2, e3);   // tf32 bit patterns (valid f32)
        }

        // ---- O += E V  (A frags from Sacc via quad shuffles) ---------------
#pragma unroll
        for (int kk2 = 0; kk2 < 4; ++kk2) {
            float c0 = sa[kk2].x, c1 = sa[kk2].y, c2 = sa[kk2].z, c3 = sa[kk2].w;
            float x00 = __shfl_sync(0xffffffffu, c0, s0);
            float x01 = __shfl_sync(0xffffffffu, c1, s0);
            float x10 = __shfl_sync(0xffffffffu, c2, s0);
            float x11 = __shfl_sync(0xffffffffu, c3, s0);
            float x20 = __shfl_sync(0xffffffffu, c0, s1);
            float x21 = __shfl_sync(0xffffffffu, c1, s1);
            float x30 = __shfl_sync(0xffffffffu, c2, s1);
            float x31 = __shfl_sync(0xffffffffu, c3, s1);
            unsigned a0 = __float_as_uint(od ? x01 : x00);
            unsigned a1 = __float_as_uint(od ? x11 : x10);
            unsigned a2 = __float_as_uint(od ? x21 : x20);
            unsigned a3 = __float_as_uint(od ? x31 : x30);
#pragma unroll
            for (int n2 = 0; n2 < 8; ++n2) {
                int vrow = 32 * wc + kk2 * 8 + m;
                unsigned bb0 = Vs[vrow * AS + n2 * 8 + g];
                unsigned bb1 = Vs[(vrow + 4) * AS + n2 * 8 + g];
                mma8(oacc[n2], a0, a1, a2, a3, bb0, bb1);
            }
        }
        __syncthreads();   // tiles dead before next load
    }

    // ---- denominator: quad-reduce + atomics --------------------------------
    if (tid < 64) den[tid] = 0.f;
    __syncthreads();
    dp0 += __shfl_xor_sync(0xffffffffu, dp0, 1);
    dp0 += __shfl_xor_sync(0xffffffffu, dp0, 2);
    dp1 += __shfl_xor_sync(0xffffffffu, dp1, 1);
    dp1 += __shfl_xor_sync(0xffffffffu, dp1, 2);
    if (m == 0) {
        atomicAdd(&den[16 * wr + g], dp0);
        atomicAdd(&den[16 * wr + g + 8], dp1);
    }
    __syncthreads();

    // ---- O reduction across the two key-half warps (Ofull overlays Ks) -----
    if (wc == 0) {
#pragma unroll
        for (int n2 = 0; n2 < 8; ++n2) {
            int r = 16 * wr + g, col = n2 * 8 + 2 * m;
            *(float2*)&Ofull[r * 64 + col]       = make_float2(oacc[n2].x, oacc[n2].y);
            *(float2*)&Ofull[(r + 8) * 64 + col] = make_float2(oacc[n2].z, oacc[n2].w);
        }
    }
    __syncthreads();
    if (wc == 1) {
#pragma unroll
        for (int n2 = 0; n2 < 8; ++n2) {
            int r = 16 * wr + g, col = n2 * 8 + 2 * m;
            float2 p0 = *(float2*)&Ofull[r * 64 + col];
            float2 p1 = *(float2*)&Ofull[(r + 8) * 64 + col];
            p0.x += oacc[n2].x; p0.y += oacc[n2].y;
            p1.x += oacc[n2].z; p1.y += oacc[n2].w;
            *(float2*)&Ofull[r * 64 + col]       = p0;
            *(float2*)&Ofull[(r + 8) * 64 + col] = p1;
        }
    }
    __syncthreads();

    // ---- normalize + coalesced writeout ------------------------------------
    float* __restrict__ Og = out + ((size_t)b * SEQ + q0) * DK;
#pragma unroll
    for (int i = 0; i < 4; ++i) {
        int e4 = tid + i * 256;        // float4 index within 64x64 tile
        int row = e4 >> 4;
        float inv = 1.0f / den[row];
        float4 o = ((const float4*)Ofull)[e4];
        o.x *= inv; o.y *= inv; o.z *= inv; o.w *= inv;
        ((float4*)Og)[e4] = o;
    }
}

// ---------------------------------------------------------------------------
extern "C" void kernel_launch(void* const* d_in, const int* in_sizes, int n_in,
                              void* d_out, int out_size)
{
    const float* q  = (const float*)d_in[0];
    const float* k  = (const float*)d_in[1];
    const float* v  = (const float*)d_in[2];
    const float* Wq = (const float*)d_in[3];
    const float* bq = (const float*)d_in[4];
    const float* Wk = (const float*)d_in[5];
    const float* bk = (const float*)d_in[6];
    const float* Wv = (const float*)d_in[7];
    const float* bv = (const float*)d_in[8];
    float* out = (float*)d_out;

    dim3 pgrid(BATCH * SEQ / 128, 1, 3);
    proj_kernel<<<pgrid, 256>>>(q, k, v, Wq, Wk, Wv, bq, bk, bv);

    dim3 agrid(SEQ / 64, BATCH);
    attn_kernel<<<agrid, 256>>>(out);
}

// round 5
// speedup vs baseline: 2.9326x; 1.3642x over previous
#include <cuda_runtime.h>
#include <math.h>

#define BATCH  4
#define SEQ    2048
#define DMODEL 1024
#define DK     64

// Scratch for projected Q/K/V: [3][B*N*DK] floats = 6 MB
__device__ float g_proj[3][BATCH * SEQ * DK];

// ---- helpers ---------------------------------------------------------------
__device__ __forceinline__ unsigned f2tf(float x) {
    unsigned u;
    asm("cvt.rna.tf32.f32 %0, %1;" : "=r"(u) : "f"(x));
    return u;
}

// D += A(16x8,row) * B(8x8,col)  tf32 inputs, f32 accumulate
__device__ __forceinline__ void mma8(float4& d,
                                     unsigned a0, unsigned a1, unsigned a2, unsigned a3,
                                     unsigned b0, unsigned b1) {
    asm("mma.sync.aligned.m16n8k8.row.col.f32.tf32.tf32.f32 "
        "{%0,%1,%2,%3},{%4,%5,%6,%7},{%8,%9},{%0,%1,%2,%3};"
        : "+f"(d.x), "+f"(d.y), "+f"(d.z), "+f"(d.w)
        : "r"(a0), "r"(a1), "r"(a2), "r"(a3), "r"(b0), "r"(b1));
}

// ---------------------------------------------------------------------------
// Projection: Y = X[8192,1024] @ W[1024,64] + b   (tf32 MMA, double-buffered)
// grid (128,1,3), 256 thr. CTA tile 64 rows x 64 cols.
// Warp (wr=wid&3, wc=wid>>2): 16 rows x 32 cols. K chunks of 32.
// ---------------------------------------------------------------------------
#define PXS 36   // Xs row stride (words): bank(a-frag) = 4g+m, conflict-free
#define PWS 72   // Ws row stride (words): bank(b-frag) = 8m+g+8n, conflict-free

__global__ __launch_bounds__(256, 1) void proj_kernel(
    const float* __restrict__ x0, const float* __restrict__ x1, const float* __restrict__ x2,
    const float* __restrict__ w0, const float* __restrict__ w1, const float* __restrict__ w2,
    const float* __restrict__ b0v, const float* __restrict__ b1v, const float* __restrict__ b2v)
{
    __shared__ unsigned Xs[2 * 64 * PXS];   // 18432 B
    __shared__ unsigned Ws[2 * 32 * PWS];   // 18432 B

    const int sel = blockIdx.z;
    const float* __restrict__ X  = (sel == 0) ? x0 : (sel == 1) ? x1 : x2;
    const float* __restrict__ W  = (sel == 0) ? w0 : (sel == 1) ? w1 : w2;
    const float* __restrict__ Bb = (sel == 0) ? b0v : (sel == 1) ? b1v : b2v;
    float* __restrict__ Y = g_proj[sel];

    const int tid  = threadIdx.x;
    const int wid  = tid >> 5;
    const int lane = tid & 31;
    const int g    = lane >> 2;
    const int m    = lane & 3;
    const int wr   = wid & 3;      // row group (16 rows)
    const int wc   = wid >> 2;     // col group (32 cols)
    const int row0 = blockIdx.x * 64;

    // per-thread load coords
    const int xr0 = tid >> 3, xc0 = (tid & 7) * 4;            // X: p=0
    const int xr1 = (256 + tid) >> 3, xc1 = xc0;              // X: p=1 (tid&7 same)
    const int wrw0 = tid >> 4, wcw0 = (tid & 15) * 4;         // W: p=0
    const int wrw1 = (256 + tid) >> 4, wcw1 = wcw0;           // W: p=1

    float4 acc[4];
#pragma unroll
    for (int n = 0; n < 4; ++n) acc[n] = make_float4(0.f, 0.f, 0.f, 0.f);

    // ---- preload chunk 0 ----
    {
        float4 xa = *(const float4*)(X + (size_t)(row0 + xr0) * DMODEL + xc0);
        float4 xb = *(const float4*)(X + (size_t)(row0 + xr1) * DMODEL + xc1);
        float4 wa = *(const float4*)(W + (size_t)wrw0 * DK + wcw0);
        float4 wb = *(const float4*)(W + (size_t)wrw1 * DK + wcw1);
        *(uint4*)&Xs[xr0 * PXS + xc0] = make_uint4(f2tf(xa.x), f2tf(xa.y), f2tf(xa.z), f2tf(xa.w));
        *(uint4*)&Xs[xr1 * PXS + xc1] = make_uint4(f2tf(xb.x), f2tf(xb.y), f2tf(xb.z), f2tf(xb.w));
        *(uint4*)&Ws[wrw0 * PWS + wcw0] = make_uint4(f2tf(wa.x), f2tf(wa.y), f2tf(wa.z), f2tf(wa.w));
        *(uint4*)&Ws[wrw1 * PWS + wcw1] = make_uint4(f2tf(wb.x), f2tf(wb.y), f2tf(wb.z), f2tf(wb.w));
    }
    __syncthreads();

    int cur = 0;
    for (int c = 0; c < 32; ++c) {
        const unsigned* Xc = Xs + cur * 64 * PXS;
        const unsigned* Wc = Ws + cur * 32 * PWS;
        const int nxt = cur ^ 1;
        unsigned* Xn = Xs + nxt * 64 * PXS;
        unsigned* Wn = Ws + nxt * 32 * PWS;

        // issue next chunk's loads
        float4 xa, xb, wa, wb;
        const bool has_next = (c + 1 < 32);
        if (has_next) {
            int k0 = (c + 1) * 32;
            xa = *(const float4*)(X + (size_t)(row0 + xr0) * DMODEL + k0 + xc0);
            xb = *(const float4*)(X + (size_t)(row0 + xr1) * DMODEL + k0 + xc1);
            wa = *(const float4*)(W + (size_t)(k0 + wrw0) * DK + wcw0);
            wb = *(const float4*)(W + (size_t)(k0 + wrw1) * DK + wcw1);
        }

        // compute on current chunk
#pragma unroll
        for (int kk = 0; kk < 4; ++kk) {
            int r = 16 * wr + g;
            unsigned a0 = Xc[r * PXS + kk * 8 + m];
            unsigned a1 = Xc[(r + 8) * PXS + kk * 8 + m];
            unsigned a2 = Xc[r * PXS + kk * 8 + m + 4];
            unsigned a3 = Xc[(r + 8) * PXS + kk * 8 + m + 4];
#pragma unroll
            for (int n = 0; n < 4; ++n) {
                int col = 32 * wc + n * 8 + g;
                unsigned bb0 = Wc[(kk * 8 + m) * PWS + col];
                unsigned bb1 = Wc[(kk * 8 + m + 4) * PWS + col];
                mma8(acc[n], a0, a1, a2, a3, bb0, bb1);
            }
        }

        // commit next chunk to smem
        if (has_next) {
            *(uint4*)&Xn[xr0 * PXS + xc0] = make_uint4(f2tf(xa.x), f2tf(xa.y), f2tf(xa.z), f2tf(xa.w));
            *(uint4*)&Xn[xr1 * PXS + xc1] = make_uint4(f2tf(xb.x), f2tf(xb.y), f2tf(xb.z), f2tf(xb.w));
            *(uint4*)&Wn[wrw0 * PWS + wcw0] = make_uint4(f2tf(wa.x), f2tf(wa.y), f2tf(wa.z), f2tf(wa.w));
            *(uint4*)&Wn[wrw1 * PWS + wcw1] = make_uint4(f2tf(wb.x), f2tf(wb.y), f2tf(wb.z), f2tf(wb.w));
        }
        __syncthreads();
        cur = nxt;
    }

    // epilogue: bias + store
#pragma unroll
    for (int n = 0; n < 4; ++n) {
        int col = 32 * wc + n * 8 + 2 * m;
        float bj0 = Bb[col], bj1 = Bb[col + 1];
        int r = row0 + 16 * wr + g;
        *(float2*)(Y + (size_t)r * DK + col)       = make_float2(acc[n].x + bj0, acc[n].y + bj1);
        *(float2*)(Y + (size_t)(r + 8) * DK + col) = make_float2(acc[n].z + bj0, acc[n].w + bj1);
    }
}

// ---------------------------------------------------------------------------
// Fused attention with tf32 MMA, double-buffered K/V tiles.
// grid (32, 4), 256 thr (8 warps). CTA: 64 q rows; loop over 64-key tiles.
// Warp (wr=wid&3, wc=wid>>2): S tile rows 16*wr x keys 32*wc..+31.
// Dynamic smem: Ks[2][64*68], Vs[2][64*72], den[64]  = 71936 B
// ---------------------------------------------------------------------------
#define KSS 68   // bank(K b-frag) = 4g+m, conflict-free
#define VSS 72   // bank(V b-frag) = 8m+g, conflict-free

extern __shared__ unsigned dyn_smem[];

__global__ __launch_bounds__(256, 1) void attn_kernel(float* __restrict__ out)
{
    unsigned* Ks = dyn_smem;                         // 2 * 64*68 = 8704 words
    unsigned* Vs = dyn_smem + 2 * 64 * KSS;          // 2 * 64*72 = 9216 words
    float*   den = (float*)(dyn_smem + 2 * 64 * KSS + 2 * 64 * VSS);
    float* Ofull = (float*)Ks;                       // 4096 words <= 8704

    const int tid  = threadIdx.x;
    const int wid  = tid >> 5;
    const int lane = tid & 31;
    const int g    = lane >> 2;
    const int m    = lane & 3;
    const int wr   = wid & 3;
    const int wc   = wid >> 2;

    const int b  = blockIdx.y;
    const int q0 = blockIdx.x * 64;

    const float* __restrict__ Qg = g_proj[0] + ((size_t)b * SEQ + q0) * DK;
    const float* __restrict__ Kg = g_proj[1] + (size_t)b * SEQ * DK;
    const float* __restrict__ Vg = g_proj[2] + (size_t)b * SEQ * DK;

    const int lr = tid >> 4, lc = (tid & 15) * 4;   // tile-load coords (p advances row by 16)

    // ---- stage Q tile through Ks buffer 0, pull A-fragments into registers --
#pragma unroll
    for (int p = 0; p < 4; ++p) {
        int r = lr + p * 16;
        float4 qv = *(const float4*)(Qg + (size_t)r * DK + lc);
        *(uint4*)&Ks[r * KSS + lc] = make_uint4(f2tf(qv.x * 0.125f), f2tf(qv.y * 0.125f),
                                                f2tf(qv.z * 0.125f), f2tf(qv.w * 0.125f));
    }
    __syncthreads();

    unsigned qa[8][4];
#pragma unroll
    for (int kk = 0; kk < 8; ++kk) {
        int r = 16 * wr + g;
        qa[kk][0] = Ks[r * KSS + kk * 8 + m];
        qa[kk][1] = Ks[(r + 8) * KSS + kk * 8 + m];
        qa[kk][2] = Ks[r * KSS + kk * 8 + m + 4];
        qa[kk][3] = Ks[(r + 8) * KSS + kk * 8 + m + 4];
    }
    __syncthreads();   // Ks free for K tiles

    float4 oacc[8];
#pragma unroll
    for (int n = 0; n < 8; ++n) oacc[n] = make_float4(0.f, 0.f, 0.f, 0.f);
    float dp0 = 0.f, dp1 = 0.f;

    const int s0  = (lane & ~3) | (m >> 1);
    const int s1  = s0 + 2;
    const bool od = (m & 1);

    // ---- preload key tile 0 -------------------------------------------------
#pragma unroll
    for (int p = 0; p < 4; ++p) {
        int r = lr + p * 16;
        float4 kv = *(const float4*)(Kg + (size_t)r * DK + lc);
        float4 vv = *(const float4*)(Vg + (size_t)r * DK + lc);
        *(uint4*)&Ks[r * KSS + lc] = make_uint4(f2tf(kv.x), f2tf(kv.y), f2tf(kv.z), f2tf(kv.w));
        *(uint4*)&Vs[r * VSS + lc] = make_uint4(f2tf(vv.x), f2tf(vv.y), f2tf(vv.z), f2tf(vv.w));
    }
    __syncthreads();

    int cur = 0;
    for (int t = 0; t < SEQ / 64; ++t) {
        const unsigned* Kc = Ks + cur * 64 * KSS;
        const unsigned* Vc = Vs + cur * 64 * VSS;
        const int nxt = cur ^ 1;

        // issue next tile's global loads
        float4 kreg[4], vreg[4];
        const bool has_next = (t + 1 < SEQ / 64);
        if (has_next) {
            int n1 = (t + 1) * 64;
#pragma unroll
            for (int p = 0; p < 4; ++p) {
                int r = lr + p * 16;
                kreg[p] = *(const float4*)(Kg + (size_t)(n1 + r) * DK + lc);
                vreg[p] = *(const float4*)(Vg + (size_t)(n1 + r) * DK + lc);
            }
        }

        // ---- S = Q K^T  (warp: 16 rows x 32 keys) --------------------------
        float4 sa[4];
#pragma unroll
        for (int n = 0; n < 4; ++n) sa[n] = make_float4(0.f, 0.f, 0.f, 0.f);
#pragma unroll
        for (int kk = 0; kk < 8; ++kk) {
#pragma unroll
            for (int n = 0; n < 4; ++n) {
                int krow = 32 * wc + n * 8 + g;
                unsigned bb0 = Kc[krow * KSS + kk * 8 + m];
                unsigned bb1 = Kc[krow * KSS + kk * 8 + m + 4];
                mma8(sa[n], qa[kk][0], qa[kk][1], qa[kk][2], qa[kk][3], bb0, bb1);
            }
        }

        // ---- exp (tf32-rounded; den uses the SAME rounded values) ----------
#pragma unroll
        for (int n = 0; n < 4; ++n) {
            float e0 = __uint_as_float(f2tf(__expf(sa[n].x)));
            float e1 = __uint_as_float(f2tf(__expf(sa[n].y)));
            float e2 = __uint_as_float(f2tf(__expf(sa[n].z)));
            float e3 = __uint_as_float(f2tf(__expf(sa[n].w)));
            dp0 += e0 + e1;
            dp1 += e2 + e3;
            sa[n] = make_float4(e0, e1, e2, e3);
        }

        // ---- O += E V  (A frags from S acc via quad shuffles) ---------------
#pragma unroll
        for (int kk2 = 0; kk2 < 4; ++kk2) {
            float c0 = sa[kk2].x, c1 = sa[kk2].y, c2 = sa[kk2].z, c3 = sa[kk2].w;
            float x00 = __shfl_sync(0xffffffffu, c0, s0);
            float x01 = __shfl_sync(0xffffffffu, c1, s0);
            float x10 = __shfl_sync(0xffffffffu, c2, s0);
            float x11 = __shfl_sync(0xffffffffu, c3, s0);
            float x20 = __shfl_sync(0xffffffffu, c0, s1);
            float x21 = __shfl_sync(0xffffffffu, c1, s1);
            float x30 = __shfl_sync(0xffffffffu, c2, s1);
            float x31 = __shfl_sync(0xffffffffu, c3, s1);
            unsigned a0 = __float_as_uint(od ? x01 : x00);
            unsigned a1 = __float_as_uint(od ? x11 : x10);
            unsigned a2 = __float_as_uint(od ? x21 : x20);
            unsigned a3 = __float_as_uint(od ? x31 : x30);
#pragma unroll
            for (int n2 = 0; n2 < 8; ++n2) {
                int vrow = 32 * wc + kk2 * 8 + m;
                unsigned bb0 = Vc[vrow * VSS + n2 * 8 + g];
                unsigned bb1 = Vc[(vrow + 4) * VSS + n2 * 8 + g];
                mma8(oacc[n2], a0, a1, a2, a3, bb0, bb1);
            }
        }

        // commit next tile to the other buffer
        if (has_next) {
            unsigned* Kn = Ks + nxt * 64 * KSS;
            unsigned* Vn = Vs + nxt * 64 * VSS;
#pragma unroll
            for (int p = 0; p < 4; ++p) {
                int r = lr + p * 16;
                *(uint4*)&Kn[r * KSS + lc] =
                    make_uint4(f2tf(kreg[p].x), f2tf(kreg[p].y), f2tf(kreg[p].z), f2tf(kreg[p].w));
                *(uint4*)&Vn[r * VSS + lc] =
                    make_uint4(f2tf(vreg[p].x), f2tf(vreg[p].y), f2tf(vreg[p].z), f2tf(vreg[p].w));
            }
        }
        __syncthreads();
        cur = nxt;
    }

    // ---- denominator: quad-reduce + atomics --------------------------------
    if (tid < 64) den[tid] = 0.f;
    __syncthreads();
    dp0 += __shfl_xor_sync(0xffffffffu, dp0, 1);
    dp0 += __shfl_xor_sync(0xffffffffu, dp0, 2);
    dp1 += __shfl_xor_sync(0xffffffffu, dp1, 1);
    dp1 += __shfl_xor_sync(0xffffffffu, dp1, 2);
    if (m == 0) {
        atomicAdd(&den[16 * wr + g], dp0);
        atomicAdd(&den[16 * wr + g + 8], dp1);
    }
    __syncthreads();

    // ---- O reduction across the two key-half warps (Ofull overlays Ks) -----
    if (wc == 0) {
#pragma unroll
        for (int n2 = 0; n2 < 8; ++n2) {
            int r = 16 * wr + g, col = n2 * 8 + 2 * m;
            *(float2*)&Ofull[r * 64 + col]       = make_float2(oacc[n2].x, oacc[n2].y);
            *(float2*)&Ofull[(r + 8) * 64 + col] = make_float2(oacc[n2].z, oacc[n2].w);
        }
    }
    __syncthreads();
    if (wc == 1) {
#pragma unroll
        for (int n2 = 0; n2 < 8; ++n2) {
            int r = 16 * wr + g, col = n2 * 8 + 2 * m;
            float2 p0 = *(float2*)&Ofull[r * 64 + col];
            float2 p1 = *(float2*)&Ofull[(r + 8) * 64 + col];
            p0.x += oacc[n2].x; p0.y += oacc[n2].y;
            p1.x += oacc[n2].z; p1.y += oacc[n2].w;
            *(float2*)&Ofull[r * 64 + col]       = p0;
            *(float2*)&Ofull[(r + 8) * 64 + col] = p1;
        }
    }
    __syncthreads();

    // ---- normalize + coalesced writeout ------------------------------------
    float* __restrict__ Og = out + ((size_t)b * SEQ + q0) * DK;
#pragma unroll
    for (int i = 0; i < 4; ++i) {
        int e4 = tid + i * 256;
        int row = e4 >> 4;
        float inv = 1.0f / den[row];
        float4 o = ((const float4*)Ofull)[e4];
        o.x *= inv; o.y *= inv; o.z *= inv; o.w *= inv;
        ((float4*)Og)[e4] = o;
    }
}

// ---------------------------------------------------------------------------
extern "C" void kernel_launch(void* const* d_in, const int* in_sizes, int n_in,
                              void* d_out, int out_size)
{
    const float* q  = (const float*)d_in[0];
    const float* k  = (const float*)d_in[1];
    const float* v  = (const float*)d_in[2];
    const float* Wq = (const float*)d_in[3];
    const float* bq = (const float*)d_in[4];
    const float* Wk = (const float*)d_in[5];
    const float* bk = (const float*)d_in[6];
    const float* Wv = (const float*)d_in[7];
    const float* bv = (const float*)d_in[8];
    float* out = (float*)d_out;

    const int asmem = (2 * 64 * KSS + 2 * 64 * VSS + 64) * 4;  // 71936 B
    cudaFuncSetAttribute(attn_kernel, cudaFuncAttributeMaxDynamicSharedMemorySize, asmem);

    dim3 pgrid(BATCH * SEQ / 64, 1, 3);
    proj_kernel<<<pgrid, 256>>>(q, k, v, Wq, Wk, Wv, bq, bk, bv);

    dim3 agrid(SEQ / 64, BATCH);
    attn_kernel<<<agrid, 256, asmem>>>(out);
}

// round 7
// speedup vs baseline: 3.0925x; 1.0545x over previous
#include <cuda_runtime.h>
#include <math.h>

#define BATCH  4
#define SEQ    2048
#define DMODEL 1024
#define DK     64

// Scratch for projected Q/K/V: [3][B*N*DK] floats = 6 MB
__device__ float g_proj[3][BATCH * SEQ * DK];

extern __shared__ unsigned dyn_smem[];

// ---- helpers ---------------------------------------------------------------
__device__ __forceinline__ unsigned f2tf(float x) {
    unsigned u;
    asm("cvt.rna.tf32.f32 %0, %1;" : "=r"(u) : "f"(x));
    return u;
}

// D += A(16x8,row) * B(8x8,col)  tf32 inputs, f32 accumulate
__device__ __forceinline__ void mma8(float4& d,
                                     unsigned a0, unsigned a1, unsigned a2, unsigned a3,
                                     unsigned b0, unsigned b1) {
    asm("mma.sync.aligned.m16n8k8.row.col.f32.tf32.tf32.f32 "
        "{%0,%1,%2,%3},{%4,%5,%6,%7},{%8,%9},{%0,%1,%2,%3};"
        : "+f"(d.x), "+f"(d.y), "+f"(d.z), "+f"(d.w)
        : "r"(a0), "r"(a1), "r"(a2), "r"(a3), "r"(b0), "r"(b1));
}

// ---------------------------------------------------------------------------
// Projection: Y = X[8192,1024] @ W[1024,64] + b   (tf32 MMA, double-buffered)
// grid (128,1,3), 256 thr. CTA tile 64 rows x 64 cols. K chunks of 64.
// Warp (wr=wid&3, wc=wid>>2): 16 rows x 32 cols.
// Dynamic smem: Xs[2][64*68] + Ws[2][64*72] = 71680 B  (3 CTAs/SM resident)
// ---------------------------------------------------------------------------
#define XS 68   // bank(a-frag) = 4g+m  -> conflict-free
#define WS 72   // bank(b-frag) = 8m+g  -> conflict-free

__global__ __launch_bounds__(256) void proj_kernel(
    const float* __restrict__ x0, const float* __restrict__ x1, const float* __restrict__ x2,
    const float* __restrict__ w0, const float* __restrict__ w1, const float* __restrict__ w2,
    const float* __restrict__ b0v, const float* __restrict__ b1v, const float* __restrict__ b2v)
{
    unsigned* Xs = dyn_smem;                    // 2 * 64*68 words
    unsigned* Ws = dyn_smem + 2 * 64 * XS;      // 2 * 64*72 words

    const int sel = blockIdx.z;
    const float* __restrict__ X  = (sel == 0) ? x0 : (sel == 1) ? x1 : x2;
    const float* __restrict__ W  = (sel == 0) ? w0 : (sel == 1) ? w1 : w2;
    const float* __restrict__ Bb = (sel == 0) ? b0v : (sel == 1) ? b1v : b2v;
    float* __restrict__ Y = g_proj[sel];

    const int tid  = threadIdx.x;
    const int wid  = tid >> 5;
    const int lane = tid & 31;
    const int g    = lane >> 2;
    const int m    = lane & 3;
    const int wr   = wid & 3;      // row group (16 rows)
    const int wc   = wid >> 2;     // col group (32 cols)
    const int row0 = blockIdx.x * 64;

    const int lr = tid >> 4, lc = (tid & 15) * 4;   // 64x64 tile loads: 4 float4/thread

    float4 acc[4];
#pragma unroll
    for (int n = 0; n < 4; ++n) acc[n] = make_float4(0.f, 0.f, 0.f, 0.f);

    // ---- preload chunk 0 ----
#pragma unroll
    for (int p = 0; p < 4; ++p) {
        int r = lr + p * 16;
        float4 xv = *(const float4*)(X + (size_t)(row0 + r) * DMODEL + lc);
        float4 wv = *(const float4*)(W + (size_t)r * DK + lc);
        *(uint4*)&Xs[r * XS + lc] = make_uint4(f2tf(xv.x), f2tf(xv.y), f2tf(xv.z), f2tf(xv.w));
        *(uint4*)&Ws[r * WS + lc] = make_uint4(f2tf(wv.x), f2tf(wv.y), f2tf(wv.z), f2tf(wv.w));
    }
    __syncthreads();

    int cur = 0;
    for (int c = 0; c < 16; ++c) {
        const unsigned* Xc = Xs + cur * 64 * XS;
        const unsigned* Wc = Ws + cur * 64 * WS;
        const int nxt = cur ^ 1;

        // issue next chunk's global loads (8 float4 in flight)
        float4 xreg[4], wreg[4];
        const bool has_next = (c + 1 < 16);
        if (has_next) {
            int k0 = (c + 1) * 64;
#pragma unroll
            for (int p = 0; p < 4; ++p) {
                int r = lr + p * 16;
                xreg[p] = *(const float4*)(X + (size_t)(row0 + r) * DMODEL + k0 + lc);
                wreg[p] = *(const float4*)(W + (size_t)(k0 + r) * DK + lc);
            }
        }

        // compute on current chunk: 8 k-steps x 4 n-tiles
#pragma unroll
        for (int kk = 0; kk < 8; ++kk) {
            int r = 16 * wr + g;
            unsigned a0 = Xc[r * XS + kk * 8 + m];
            unsigned a1 = Xc[(r + 8) * XS + kk * 8 + m];
            unsigned a2 = Xc[r * XS + kk * 8 + m + 4];
            unsigned a3 = Xc[(r + 8) * XS + kk * 8 + m + 4];
#pragma unroll
            for (int n = 0; n < 4; ++n) {
                int col = 32 * wc + n * 8 + g;
                unsigned bb0 = Wc[(kk * 8 + m) * WS + col];
                unsigned bb1 = Wc[(kk * 8 + m + 4) * WS + col];
                mma8(acc[n], a0, a1, a2, a3, bb0, bb1);
            }
        }

        // commit next chunk
        if (has_next) {
            unsigned* Xn = Xs + nxt * 64 * XS;
            unsigned* Wn = Ws + nxt * 64 * WS;
#pragma unroll
            for (int p = 0; p < 4; ++p) {
                int r = lr + p * 16;
                *(uint4*)&Xn[r * XS + lc] =
                    make_uint4(f2tf(xreg[p].x), f2tf(xreg[p].y), f2tf(xreg[p].z), f2tf(xreg[p].w));
                *(uint4*)&Wn[r * WS + lc] =
                    make_uint4(f2tf(wreg[p].x), f2tf(wreg[p].y), f2tf(wreg[p].z), f2tf(wreg[p].w));
            }
        }
        __syncthreads();
        cur = nxt;
    }

    // epilogue: bias + store
#pragma unroll
    for (int n = 0; n < 4; ++n) {
        int col = 32 * wc + n * 8 + 2 * m;
        float bj0 = Bb[col], bj1 = Bb[col + 1];
        int r = row0 + 16 * wr + g;
        *(float2*)(Y + (size_t)r * DK + col)       = make_float2(acc[n].x + bj0, acc[n].y + bj1);
        *(float2*)(Y + (size_t)(r + 8) * DK + col) = make_float2(acc[n].z + bj0, acc[n].w + bj1);
    }
}

// ---------------------------------------------------------------------------
// Fused attention with tf32 MMA, double-buffered K/V tiles, 16 warps.
// grid (32, 4), 512 thr. CTA: 64 q rows; loop over 64-key tiles.
// Warp (wr=wid&3, wkc=wid>>2): S tile rows 16*wr x keys 16*wkc..+15.
// Dynamic smem: Ks[2][64*68], Vs[2][64*72], den[64] = 71936 B
// ---------------------------------------------------------------------------
#define KSS 68   // bank(K b-frag) = 4g+m, conflict-free
#define VSS 72   // bank(V b-frag) = 8m+g, conflict-free

__global__ __launch_bounds__(512, 1) void attn_kernel(float* __restrict__ out)
{
    unsigned* Ks = dyn_smem;                         // 2 * 64*68 words
    unsigned* Vs = dyn_smem + 2 * 64 * KSS;          // 2 * 64*72 words
    float*   den = (float*)(dyn_smem + 2 * 64 * KSS + 2 * 64 * VSS);
    float* Of0 = (float*)Ks;                         // 4096 words <= 8704
    float* Of1 = (float*)Vs;                         // 4096 words <= 9216

    const int tid  = threadIdx.x;
    const int wid  = tid >> 5;
    const int lane = tid & 31;
    const int g    = lane >> 2;
    const int m    = lane & 3;
    const int wr   = wid & 3;      // q-row group (16 rows)
    const int wkc  = wid >> 2;     // key group (16 keys)

    const int b  = blockIdx.y;
    const int q0 = blockIdx.x * 64;

    const float* __restrict__ Qg = g_proj[0] + ((size_t)b * SEQ + q0) * DK;
    const float* __restrict__ Kg = g_proj[1] + (size_t)b * SEQ * DK;
    const float* __restrict__ Vg = g_proj[2] + (size_t)b * SEQ * DK;

    const int lr = tid >> 4, lc = (tid & 15) * 4;   // 64x64 tile: 2 float4/thread (rows lr, lr+32)

    if (tid < 64) den[tid] = 0.f;

    // ---- stage Q tile through Ks buffer 0, pull A-fragments into registers --
#pragma unroll
    for (int p = 0; p < 2; ++p) {
        int r = lr + p * 32;
        float4 qv = *(const float4*)(Qg + (size_t)r * DK + lc);
        *(uint4*)&Ks[r * KSS + lc] = make_uint4(f2tf(qv.x * 0.125f), f2tf(qv.y * 0.125f),
                                                f2tf(qv.z * 0.125f), f2tf(qv.w * 0.125f));
    }
    __syncthreads();

    unsigned qa[8][4];
#pragma unroll
    for (int kk = 0; kk < 8; ++kk) {
        int r = 16 * wr + g;
        qa[kk][0] = Ks[r * KSS + kk * 8 + m];
        qa[kk][1] = Ks[(r + 8) * KSS + kk * 8 + m];
        qa[kk][2] = Ks[r * KSS + kk * 8 + m + 4];
        qa[kk][3] = Ks[(r + 8) * KSS + kk * 8 + m + 4];
    }
    __syncthreads();   // Ks free for K tiles

    float4 oacc[8];
#pragma unroll
    for (int n = 0; n < 8; ++n) oacc[n] = make_float4(0.f, 0.f, 0.f, 0.f);
    float dp0 = 0.f, dp1 = 0.f;

    const int s0  = (lane & ~3) | (m >> 1);
    const int s1  = s0 + 2;
    const bool od = (m & 1);

    // ---- preload key tile 0 -------------------------------------------------
#pragma unroll
    for (int p = 0; p < 2; ++p) {
        int r = lr + p * 32;
        float4 kv = *(const float4*)(Kg + (size_t)r * DK + lc);
        float4 vv = *(const float4*)(Vg + (size_t)r * DK + lc);
        *(uint4*)&Ks[r * KSS + lc] = make_uint4(f2tf(kv.x), f2tf(kv.y), f2tf(kv.z), f2tf(kv.w));
        *(uint4*)&Vs[r * VSS + lc] = make_uint4(f2tf(vv.x), f2tf(vv.y), f2tf(vv.z), f2tf(vv.w));
    }
    __syncthreads();

    int cur = 0;
    for (int t = 0; t < SEQ / 64; ++t) {
        const unsigned* Kc = Ks + cur * 64 * KSS;
        const unsigned* Vc = Vs + cur * 64 * VSS;
        const int nxt = cur ^ 1;

        // issue next tile's global loads
        float4 kreg[2], vreg[2];
        const bool has_next = (t + 1 < SEQ / 64);
        if (has_next) {
            int n1 = (t + 1) * 64;
#pragma unroll
            for (int p = 0; p < 2; ++p) {
                int r = lr + p * 32;
                kreg[p] = *(const float4*)(Kg + (size_t)(n1 + r) * DK + lc);
                vreg[p] = *(const float4*)(Vg + (size_t)(n1 + r) * DK + lc);
            }
        }

        // ---- S = Q K^T  (warp: 16 rows x 16 keys) --------------------------
        float4 sa[2];
        sa[0] = make_float4(0.f, 0.f, 0.f, 0.f);
        sa[1] = make_float4(0.f, 0.f, 0.f, 0.f);
#pragma unroll
        for (int kk = 0; kk < 8; ++kk) {
#pragma unroll
            for (int n = 0; n < 2; ++n) {
                int krow = 16 * wkc + n * 8 + g;
                unsigned bb0 = Kc[krow * KSS + kk * 8 + m];
                unsigned bb1 = Kc[krow * KSS + kk * 8 + m + 4];
                mma8(sa[n], qa[kk][0], qa[kk][1], qa[kk][2], qa[kk][3], bb0, bb1);
            }
        }

        // ---- exp (tf32-rounded; den uses the SAME rounded values) ----------
#pragma unroll
        for (int n = 0; n < 2; ++n) {
            float e0 = __uint_as_float(f2tf(__expf(sa[n].x)));
            float e1 = __uint_as_float(f2tf(__expf(sa[n].y)));
            float e2 = __uint_as_float(f2tf(__expf(sa[n].z)));
            float e3 = __uint_as_float(f2tf(__expf(sa[n].w)));
            dp0 += e0 + e1;
            dp1 += e2 + e3;
            sa[n] = make_float4(e0, e1, e2, e3);
        }

        // ---- O += E V  (A frags from S acc via quad shuffles) ---------------
#pragma unroll
        for (int kk2 = 0; kk2 < 2; ++kk2) {
            float c0 = sa[kk2].x, c1 = sa[kk2].y, c2 = sa[kk2].z, c3 = sa[kk2].w;
            float x00 = __shfl_sync(0xffffffffu, c0, s0);
            float x01 = __shfl_sync(0xffffffffu, c1, s0);
            float x10 = __shfl_sync(0xffffffffu, c2, s0);
            float x11 = __shfl_sync(0xffffffffu, c3, s0);
            float x20 = __shfl_sync(0xffffffffu, c0, s1);
            float x21 = __shfl_sync(0xffffffffu, c1, s1);
            float x30 = __shfl_sync(0xffffffffu, c2, s1);
            float x31 = __shfl_sync(0xffffffffu, c3, s1);
            unsigned a0 = __float_as_uint(od ? x01 : x00);
            unsigned a1 = __float_as_uint(od ? x11 : x10);
            unsigned a2 = __float_as_uint(od ? x21 : x20);
            unsigned a3 = __float_as_uint(od ? x31 : x30);
#pragma unroll
            for (int n2 = 0; n2 < 8; ++n2) {
                int vrow = 16 * wkc + kk2 * 8 + m;
                unsigned bb0 = Vc[vrow * VSS + n2 * 8 + g];
                unsigned bb1 = Vc[(vrow + 4) * VSS + n2 * 8 + g];
                mma8(oacc[n2], a0, a1, a2, a3, bb0, bb1);
            }
        }

        // commit next tile
        if (has_next) {
            unsigned* Kn = Ks + nxt * 64 * KSS;
            unsigned* Vn = Vs + nxt * 64 * VSS;
#pragma unroll
            for (int p = 0; p < 2; ++p) {
                int r = lr + p * 32;
                *(uint4*)&Kn[r * KSS + lc] =
                    make_uint4(f2tf(kreg[p].x), f2tf(kreg[p].y), f2tf(kreg[p].z), f2tf(kreg[p].w));
                *(uint4*)&Vn[r * VSS + lc] =
                    make_uint4(f2tf(vreg[p].x), f2tf(vreg[p].y), f2tf(vreg[p].z), f2tf(vreg[p].w));
            }
        }
        __syncthreads();
        cur = nxt;
    }

    // ---- denominator: quad-reduce + atomics --------------------------------
    dp0 += __shfl_xor_sync(0xffffffffu, dp0, 1);
    dp0 += __shfl_xor_sync(0xffffffffu, dp0, 2);
    dp1 += __shfl_xor_sync(0xffffffffu, dp1, 1);
    dp1 += __shfl_xor_sync(0xffffffffu, dp1, 2);
    if (m == 0) {
        atomicAdd(&den[16 * wr + g], dp0);
        atomicAdd(&den[16 * wr + g + 8], dp1);
    }

    // ---- O reduction: key groups 0,1 write; 2,3 add (two parallel buffers) --
    if (wkc == 0) {
#pragma unroll
        for (int n2 = 0; n2 < 8; ++n2) {
            int r = 16 * wr + g, col = n2 * 8 + 2 * m;
            *(float2*)&Of0[r * 64 + col]       = make_float2(oacc[n2].x, oacc[n2].y);
            *(float2*)&Of0[(r + 8) * 64 + col] = make_float2(oacc[n2].z, oacc[n2].w);
        }
    } else if (wkc == 1) {
#pragma unroll
        for (int n2 = 0; n2 < 8; ++n2) {
            int r = 16 * wr + g, col = n2 * 8 + 2 * m;
            *(float2*)&Of1[r * 64 + col]       = make_float2(oacc[n2].x, oacc[n2].y);
            *(float2*)&Of1[(r + 8) * 64 + col] = make_float2(oacc[n2].z, oacc[n2].w);
        }
    }
    __syncthreads();
    if (wkc == 2) {
#pragma unroll
        for (int n2 = 0; n2 < 8; ++n2) {
            int r = 16 * wr + g, col = n2 * 8 + 2 * m;
            float2 p0 = *(float2*)&Of0[r * 64 + col];
            float2 p1 = *(float2*)&Of0[(r + 8) * 64 + col];
            p0.x += oacc[n2].x; p0.y += oacc[n2].y;
            p1.x += oacc[n2].z; p1.y += oacc[n2].w;
            *(float2*)&Of0[r * 64 + col]       = p0;
            *(float2*)&Of0[(r + 8) * 64 + col] = p1;
        }
    } else if (wkc == 3) {
#pragma unroll
        for (int n2 = 0; n2 < 8; ++n2) {
            int r = 16 * wr + g, col = n2 * 8 + 2 * m;
            float2 p0 = *(float2*)&Of1[r * 64 + col];
            float2 p1 = *(float2*)&Of1[(r + 8) * 64 + col];
            p0.x += oacc[n2].x; p0.y += oacc[n2].y;
            p1.x += oacc[n2].z; p1.y += oacc[n2].w;
            *(float2*)&Of1[r * 64 + col]       = p0;
            *(float2*)&Of1[(r + 8) * 64 + col] = p1;
        }
    }
    __syncthreads();

    // ---- normalize + coalesced writeout ------------------------------------
    float* __restrict__ Og = out + ((size_t)b * SEQ + q0) * DK;
#pragma unroll
    for (int i = 0; i < 2; ++i) {
        int e4 = tid + i * 512;            // float4 index within 64x64 tile
        int row = e4 >> 4;
        float inv = 1.0f / den[row];
        float4 oa = ((const float4*)Of0)[e4];
        float4 ob = ((const float4*)Of1)[e4];
        float4 o;
        o.x = (oa.x + ob.x) * inv;
        o.y = (oa.y + ob.y) * inv;
        o.z = (oa.z + ob.z) * inv;
        o.w = (oa.w + ob.w) * inv;
        ((float4*)Og)[e4] = o;
    }
}

// ---------------------------------------------------------------------------
extern "C" void kernel_launch(void* const* d_in, const int* in_sizes, int n_in,
                              void* d_out, int out_size)
{
    const float* q  = (const float*)d_in[0];
    const float* k  = (const float*)d_in[1];
    const float* v  = (const float*)d_in[2];
    const float* Wq = (const float*)d_in[3];
    const float* bq = (const float*)d_in[4];
    const float* Wk = (const float*)d_in[5];
    const float* bk = (const float*)d_in[6];
    const float* Wv = (const float*)d_in[7];
    const float* bv = (const float*)d_in[8];
    float* out = (float*)d_out;

    const int psmem = (2 * 64 * XS + 2 * 64 * WS) * 4;             // 71680 B
    const int asmem = (2 * 64 * KSS + 2 * 64 * VSS + 64) * 4;      // 71936 B
    cudaFuncSetAttribute(proj_kernel, cudaFuncAttributeMaxDynamicSharedMemorySize, psmem);
    cudaFuncSetAttribute(attn_kernel, cudaFuncAttributeMaxDynamicSharedMemorySize, asmem);

    dim3 pgrid(BATCH * SEQ / 64, 1, 3);
    proj_kernel<<<pgrid, 256, psmem>>>(q, k, v, Wq, Wk, Wv, bq, bk, bv);

    dim3 agrid(SEQ / 64, BATCH);
    attn_kernel<<<agrid, 512, asmem>>>(out);
}

// round 12
// speedup vs baseline: 3.2780x; 1.0600x over previous
#include <cuda_runtime.h>
#include <cstdint>
#include <math.h>

#define BATCH  4
#define SEQ    2048
#define DMODEL 1024
#define DK     64

// Scratch: projected Q/K/V as tf32 bit patterns.
// Q: pre-scaled by 0.125.  Q and K: d-columns permuted within each aligned
// 8-group (j<4 -> 2j, else 2(j-4)+1) so MMA k-fragment pairs are adjacent.
// V: linear.  W pre-converted to tf32 (layout [k*DK + n]).
__device__ unsigned g_proj[3][BATCH * SEQ * DK];
__device__ unsigned g_wtf[3][DMODEL * DK];

extern __shared__ unsigned dyn_smem[];

// ---- helpers ---------------------------------------------------------------
__device__ __forceinline__ unsigned f2tf(float x) {
    unsigned u;
    asm("cvt.rna.tf32.f32 %0, %1;" : "=r"(u) : "f"(x));
    return u;
}

__device__ __forceinline__ void mma8(float4& d,
                                     unsigned a0, unsigned a1, unsigned a2, unsigned a3,
                                     unsigned b0, unsigned b1) {
    asm("mma.sync.aligned.m16n8k8.row.col.f32.tf32.tf32.f32 "
        "{%0,%1,%2,%3},{%4,%5,%6,%7},{%8,%9},{%0,%1,%2,%3};"
        : "+f"(d.x), "+f"(d.y), "+f"(d.z), "+f"(d.w)
        : "r"(a0), "r"(a1), "r"(a2), "r"(a3), "r"(b0), "r"(b1));
}

__device__ __forceinline__ uint32_t smem_u32(const void* p) {
    return (uint32_t)__cvta_generic_to_shared(p);
}
__device__ __forceinline__ void cp_async16(uint32_t dst, const void* src) {
    asm volatile("cp.async.cg.shared.global [%0], [%1], 16;" :: "r"(dst), "l"(src) : "memory");
}
__device__ __forceinline__ void cp_commit() {
    asm volatile("cp.async.commit_group;" ::: "memory");
}
__device__ __forceinline__ void cp_wait0() {
    asm volatile("cp.async.wait_group 0;" ::: "memory");
}

// ===========================================================================
// wprep: W f32 [k][n] -> tf32 bit patterns, same layout
// ===========================================================================
__global__ __launch_bounds__(256) void wprep_kernel(
    const float* __restrict__ w0, const float* __restrict__ w1, const float* __restrict__ w2)
{
    const int sel = blockIdx.z;
    const float* __restrict__ W = (sel == 0) ? w0 : (sel == 1) ? w1 : w2;
    for (int idx = blockIdx.x * 256 + threadIdx.x; idx < DMODEL * DK; idx += 32 * 256) {
        g_wtf[sel][idx] = f2tf(W[idx]);
    }
}

// ===========================================================================
// Projection: Y = tf32(X @ W + b), Q scaled by 0.125.  tf32 mma.sync.
// grid (128,1,3), 256 thr. CTA tile 64 rows x 64 cols, K chunks of 64.
// X: LDG f32 -> rna cvt -> STS (double buffered).  W: cp.async (pre-rounded).
// Q/K outputs written with the d-column pair permutation; V linear.
// ===========================================================================
#define XS 68   // bank(a-frag) = 4g+m  -> conflict-free
#define WS 72   // bank(b-frag) = 8m+g  -> conflict-free; 72*4=288 (16B multiple)

__global__ __launch_bounds__(256) void proj_kernel(
    const float* __restrict__ x0, const float* __restrict__ x1, const float* __restrict__ x2,
    const float* __restrict__ b0v, const float* __restrict__ b1v, const float* __restrict__ b2v)
{
    unsigned* Xs = dyn_smem;                    // 2 * 64*68 words
    unsigned* Ws = dyn_smem + 2 * 64 * XS;      // 2 * 64*72 words
    const uint32_t ws_u32 = smem_u32(Ws);

    const int sel = blockIdx.z;
    const float* __restrict__ X  = (sel == 0) ? x0 : (sel == 1) ? x1 : x2;
    const float* __restrict__ Bb = (sel == 0) ? b0v : (sel == 1) ? b1v : b2v;
    const unsigned* __restrict__ Wt = g_wtf[sel];
    unsigned* __restrict__ Y = g_proj[sel];
    const float oscale = (sel == 0) ? 0.125f : 1.0f;

    const int tid  = threadIdx.x;
    const int wid  = tid >> 5;
    const int lane = tid & 31;
    const int g    = lane >> 2;
    const int m    = lane & 3;
    const int wr   = wid & 3;      // row group (16 rows)
    const int wc   = wid >> 2;     // col group (32 cols)
    const int row0 = blockIdx.x * 64;

    const int lr = tid >> 4;
    const int lc = (tid & 15) * 4;

    float4 acc[4];
#pragma unroll
    for (int n = 0; n < 4; ++n) acc[n] = make_float4(0.f, 0.f, 0.f, 0.f);

    // ---- prefetch chunk 0: X into regs, W via cp.async ----
    float4 xr[4];
#pragma unroll
    for (int p = 0; p < 4; ++p) {
        int r = lr + p * 16;
        xr[p] = *(const float4*)(X + (size_t)(row0 + r) * DMODEL + lc);
        cp_async16(ws_u32 + (uint32_t)(r * WS + lc) * 4, Wt + (size_t)r * DK + lc);
    }
    cp_commit();
    // store X chunk 0
#pragma unroll
    for (int p = 0; p < 4; ++p) {
        int r = lr + p * 16;
        *(uint4*)&Xs[r * XS + lc] =
            make_uint4(f2tf(xr[p].x), f2tf(xr[p].y), f2tf(xr[p].z), f2tf(xr[p].w));
    }
    cp_wait0();
    __syncthreads();

    int cur = 0;
    for (int c = 0; c < 16; ++c) {
        const unsigned* Xc = Xs + cur * 64 * XS;
        const unsigned* Wc = Ws + cur * 64 * WS;
        const int nxt = cur ^ 1;
        const bool has_next = (c + 1 < 16);

        // issue next chunk: X LDGs into regs, W cp.asyncs
        if (has_next) {
            const int k0 = (c + 1) * 64;
#pragma unroll
            for (int p = 0; p < 4; ++p) {
                int r = lr + p * 16;
                xr[p] = *(const float4*)(X + (size_t)(row0 + r) * DMODEL + k0 + lc);
                cp_async16(ws_u32 + (uint32_t)(nxt * 64 * WS + r * WS + lc) * 4,
                           Wt + (size_t)(k0 + r) * DK + lc);
            }
            cp_commit();
        }

        // compute current chunk: 8 k-steps x 4 n-tiles
#pragma unroll
        for (int kk = 0; kk < 8; ++kk) {
            int r = 16 * wr + g;
            unsigned a0 = Xc[r * XS + kk * 8 + m];
            unsigned a1 = Xc[(r + 8) * XS + kk * 8 + m];
            unsigned a2 = Xc[r * XS + kk * 8 + m + 4];
            unsigned a3 = Xc[(r + 8) * XS + kk * 8 + m + 4];
#pragma unroll
            for (int n = 0; n < 4; ++n) {
                int col = 32 * wc + n * 8 + g;
                unsigned bb0 = Wc[(kk * 8 + m) * WS + col];
                unsigned bb1 = Wc[(kk * 8 + m + 4) * WS + col];
                mma8(acc[n], a0, a1, a2, a3, bb0, bb1);
            }
        }

        // store next X chunk (cvt + STS), then converge
        if (has_next) {
            unsigned* Xn = Xs + nxt * 64 * XS;
#pragma unroll
            for (int p = 0; p < 4; ++p) {
                int r = lr + p * 16;
                *(uint4*)&Xn[r * XS + lc] =
                    make_uint4(f2tf(xr[p].x), f2tf(xr[p].y), f2tf(xr[p].z), f2tf(xr[p].w));
            }
        }
        cp_wait0();
        __syncthreads();
        cur = nxt;
    }

    // epilogue: bias, scale, round to tf32 bits, store.
    // Q/K (sel 0,1): permuted columns (logical 2m -> pos0, 2m+1 -> pos0+2).
    // V (sel 2): linear.
#pragma unroll
    for (int n = 0; n < 4; ++n) {
        int col = 32 * wc + n * 8 + 2 * m;
        float bj0 = Bb[col];
        float bj1 = Bb[col + 1];
        int r = row0 + 16 * wr + g;
        unsigned o00 = f2tf((acc[n].x + bj0) * oscale);
        unsigned o01 = f2tf((acc[n].y + bj1) * oscale);
        unsigned o10 = f2tf((acc[n].z + bj0) * oscale);
        unsigned o11 = f2tf((acc[n].w + bj1) * oscale);
        if (sel == 2) {
            *(uint2*)(Y + (size_t)r * DK + col)       = make_uint2(o00, o01);
            *(uint2*)(Y + (size_t)(r + 8) * DK + col) = make_uint2(o10, o11);
        } else {
            int base = 32 * wc + n * 8;
            int pos0 = (m < 2) ? 4 * m : 4 * m - 7;   // perm of j=2m
            Y[(size_t)r * DK + base + pos0]           = o00;
            Y[(size_t)r * DK + base + pos0 + 2]       = o01;
            Y[(size_t)(r + 8) * DK + base + pos0]     = o10;
            Y[(size_t)(r + 8) * DK + base + pos0 + 2] = o11;
        }
    }
}

// ===========================================================================
// Fused attention: inputs tf32 bits (Q pre-scaled, Q/K column-pair-permuted).
// cp.async K/V, double-buffered, 512 thr / 16 warps.  tf32 mma.sync.
// S-GEMM fragment pairs load as single LDS.64 (conflict-free).
// ===========================================================================
#define KSS 68   // 68*4=272, 16B multiple
#define VSS 72   // 72*4=288, 16B multiple

__global__ __launch_bounds__(512, 1) void attn_kernel(float* __restrict__ out)
{
    unsigned* Ks = dyn_smem;                         // 2 * 64*68 words
    unsigned* Vs = dyn_smem + 2 * 64 * KSS;          // 2 * 64*72 words
    float* den = (float*)(dyn_smem + 2 * 64 * KSS + 2 * 64 * VSS);
    float* Of0 = (float*)Ks;                         // 4096 words <= 8704
    float* Of1 = (float*)Vs;                         // 4096 words <= 9216
    const uint32_t ks_u32 = smem_u32(Ks);
    const uint32_t vs_u32 = smem_u32(Vs);

    const int tid  = threadIdx.x;
    const int wid  = tid >> 5;
    const int lane = tid & 31;
    const int g    = lane >> 2;
    const int m    = lane & 3;
    const int wr   = wid & 3;      // q-row group (16 rows)
    const int wkc  = wid >> 2;     // key group (16 keys)

    const int b  = blockIdx.y;
    const int q0 = blockIdx.x * 64;

    const unsigned* __restrict__ Qg = g_proj[0] + ((size_t)b * SEQ + q0) * DK;
    const unsigned* __restrict__ Kg = g_proj[1] + (size_t)b * SEQ * DK;
    const unsigned* __restrict__ Vg = g_proj[2] + (size_t)b * SEQ * DK;

    const int lr = tid >> 4;
    const int lc = (tid & 15) * 4;

    if (tid < 64) den[tid] = 0.f;

    // ---- stage Q tile (permuted tf32 bits) through Ks buffer 0 -------------
#pragma unroll
    for (int p = 0; p < 2; ++p) {
        int r = lr + p * 32;
        *(uint4*)&Ks[r * KSS + lc] = *(const uint4*)(Qg + (size_t)r * DK + lc);
    }
    __syncthreads();

    // a-fragment pairs are adjacent under the permutation: one LDS.64 each
    unsigned qa[8][4];
#pragma unroll
    for (int kk = 0; kk < 8; ++kk) {
        int r = 16 * wr + g;
        uint2 qlo = *(const uint2*)&Ks[r * KSS + kk * 8 + 2 * m];
        uint2 qhi = *(const uint2*)&Ks[(r + 8) * KSS + kk * 8 + 2 * m];
        qa[kk][0] = qlo.x;
        qa[kk][2] = qlo.y;
        qa[kk][1] = qhi.x;
        qa[kk][3] = qhi.y;
    }
    __syncthreads();   // Ks free for K tiles

    float4 oacc[8];
#pragma unroll
    for (int n = 0; n < 8; ++n) {
        oacc[n] = make_float4(0.f, 0.f, 0.f, 0.f);
    }
    float dp0 = 0.f;
    float dp1 = 0.f;

    const int s0 = (lane & ~3) | (m >> 1);
    const int s1 = s0 + 2;
    const bool od = (m & 1);

    // ---- preload key tile 0 via cp.async -----------------------------------
#pragma unroll
    for (int p = 0; p < 2; ++p) {
        int r = lr + p * 32;
        cp_async16(ks_u32 + (uint32_t)(r * KSS + lc) * 4, Kg + (size_t)r * DK + lc);
        cp_async16(vs_u32 + (uint32_t)(r * VSS + lc) * 4, Vg + (size_t)r * DK + lc);
    }
    cp_commit();

    int cur = 0;
    for (int t = 0; t < SEQ / 64; ++t) {
        cp_wait0();
        __syncthreads();   // current buffer's data visible to all

        const unsigned* Kc = Ks + cur * 64 * KSS;
        const unsigned* Vc = Vs + cur * 64 * VSS;
        const int nxt = cur ^ 1;

        // issue next tile's async copies (fully overlapped with compute)
        if (t + 1 < SEQ / 64) {
            int n1 = (t + 1) * 64;
#pragma unroll
            for (int p = 0; p < 2; ++p) {
                int r = lr + p * 32;
                cp_async16(ks_u32 + (uint32_t)(nxt * 64 * KSS + r * KSS + lc) * 4,
                           Kg + (size_t)(n1 + r) * DK + lc);
                cp_async16(vs_u32 + (uint32_t)(nxt * 64 * VSS + r * VSS + lc) * 4,
                           Vg + (size_t)(n1 + r) * DK + lc);
            }
            cp_commit();
        }

        // ---- S = Q K^T  (warp: 16 rows x 16 keys); paired K b-frags --------
        float4 sa[2];
        sa[0] = make_float4(0.f, 0.f, 0.f, 0.f);
        sa[1] = make_float4(0.f, 0.f, 0.f, 0.f);
#pragma unroll
        for (int kk = 0; kk < 8; ++kk) {
#pragma unroll
            for (int n = 0; n < 2; ++n) {
                int krow = 16 * wkc + n * 8 + g;
                uint2 kb = *(const uint2*)&Kc[krow * KSS + kk * 8 + 2 * m];
                mma8(sa[n], qa[kk][0], qa[kk][1], qa[kk][2], qa[kk][3], kb.x, kb.y);
            }
        }

        // ---- exp (tf32-rounded; den uses the SAME rounded values) ----------
#pragma unroll
        for (int n = 0; n < 2; ++n) {
            float e0 = __uint_as_float(f2tf(__expf(sa[n].x)));
            float e1 = __uint_as_float(f2tf(__expf(sa[n].y)));
            float e2 = __uint_as_float(f2tf(__expf(sa[n].z)));
            float e3 = __uint_as_float(f2tf(__expf(sa[n].w)));
            dp0 += e0 + e1;
            dp1 += e2 + e3;
            sa[n] = make_float4(e0, e1, e2, e3);
        }

        // ---- O += E V  (A frags from S acc via quad shuffles) ---------------
#pragma unroll
        for (int kk2 = 0; kk2 < 2; ++kk2) {
            float c0 = sa[kk2].x;
            float c1 = sa[kk2].y;
            float c2 = sa[kk2].z;
            float c3 = sa[kk2].w;
            float x00 = __shfl_sync(0xffffffffu, c0, s0);
            float x01 = __shfl_sync(0xffffffffu, c1, s0);
            float x10 = __shfl_sync(0xffffffffu, c2, s0);
            float x11 = __shfl_sync(0xffffffffu, c3, s0);
            float x20 = __shfl_sync(0xffffffffu, c0, s1);
            float x21 = __shfl_sync(0xffffffffu, c1, s1);
            float x30 = __shfl_sync(0xffffffffu, c2, s1);
            float x31 = __shfl_sync(0xffffffffu, c3, s1);
            unsigned a0 = __float_as_uint(od ? x01 : x00);
            unsigned a1 = __float_as_uint(od ? x11 : x10);
            unsigned a2 = __float_as_uint(od ? x21 : x20);
            unsigned a3 = __float_as_uint(od ? x31 : x30);
#pragma unroll
            for (int n2 = 0; n2 < 8; ++n2) {
                int vrow = 16 * wkc + kk2 * 8 + m;
                unsigned bb0 = Vc[vrow * VSS + n2 * 8 + g];
                unsigned bb1 = Vc[(vrow + 4) * VSS + n2 * 8 + g];
                mma8(oacc[n2], a0, a1, a2, a3, bb0, bb1);
            }
        }

        cur = nxt;
    }
    __syncthreads();   // all warps done with final tile buffers

    // ---- denominator: quad-reduce + atomics --------------------------------
    dp0 += __shfl_xor_sync(0xffffffffu, dp0, 1);
    dp0 += __shfl_xor_sync(0xffffffffu, dp0, 2);
    dp1 += __shfl_xor_sync(0xffffffffu, dp1, 1);
    dp1 += __shfl_xor_sync(0xffffffffu, dp1, 2);
    if (m == 0) {
        atomicAdd(&den[16 * wr + g], dp0);
        atomicAdd(&den[16 * wr + g + 8], dp1);
    }

    // ---- O reduction: key groups 0,1 write; 2,3 add ------------------------
    if (wkc == 0) {
#pragma unroll
        for (int n2 = 0; n2 < 8; ++n2) {
            int r = 16 * wr + g;
            int col = n2 * 8 + 2 * m;
            *(float2*)&Of0[r * 64 + col]       = make_float2(oacc[n2].x, oacc[n2].y);
            *(float2*)&Of0[(r + 8) * 64 + col] = make_float2(oacc[n2].z, oacc[n2].w);
        }
    } else if (wkc == 1) {
#pragma unroll
        for (int n2 = 0; n2 < 8; ++n2) {
            int r = 16 * wr + g;
            int col = n2 * 8 + 2 * m;
            *(float2*)&Of1[r * 64 + col]       = make_float2(oacc[n2].x, oacc[n2].y);
            *(float2*)&Of1[(r + 8) * 64 + col] = make_float2(oacc[n2].z, oacc[n2].w);
        }
    }
    __syncthreads();
    if (wkc == 2) {
#pragma unroll
        for (int n2 = 0; n2 < 8; ++n2) {
            int r = 16 * wr + g;
            int col = n2 * 8 + 2 * m;
            float2 p0 = *(float2*)&Of0[r * 64 + col];
            float2 p1 = *(float2*)&Of0[(r + 8) * 64 + col];
            p0.x += oacc[n2].x; p0.y += oacc[n2].y;
            p1.x += oacc[n2].z; p1.y += oacc[n2].w;
            *(float2*)&Of0[r * 64 + col]       = p0;
            *(float2*)&Of0[(r + 8) * 64 + col] = p1;
        }
    } else if (wkc == 3) {
#pragma unroll
        for (int n2 = 0; n2 < 8; ++n2) {
            int r = 16 * wr + g;
            int col = n2 * 8 + 2 * m;
            float2 p0 = *(float2*)&Of1[r * 64 + col];
            float2 p1 = *(float2*)&Of1[(r + 8) * 64 + col];
            p0.x += oacc[n2].x; p0.y += oacc[n2].y;
            p1.x += oacc[n2].z; p1.y += oacc[n2].w;
            *(float2*)&Of1[r * 64 + col]       = p0;
            *(float2*)&Of1[(r + 8) * 64 + col] = p1;
        }
    }
    __syncthreads();

    // ---- normalize + coalesced writeout ------------------------------------
    float* __restrict__ Og = out + ((size_t)b * SEQ + q0) * DK;
#pragma unroll
    for (int i = 0; i < 2; ++i) {
        int e4 = tid + i * 512;
        int row = e4 >> 4;
        float inv = 1.0f / den[row];
        float4 oa = ((const float4*)Of0)[e4];
        float4 ob = ((const float4*)Of1)[e4];
        float4 o;
        o.x = (oa.x + ob.x) * inv;
        o.y = (oa.y + ob.y) * inv;
        o.z = (oa.z + ob.z) * inv;
        o.w = (oa.w + ob.w) * inv;
        ((float4*)Og)[e4] = o;
    }
}

// ---------------------------------------------------------------------------
extern "C" void kernel_launch(void* const* d_in, const int* in_sizes, int n_in,
                              void* d_out, int out_size)
{
    const float* q  = (const float*)d_in[0];
    const float* k  = (const float*)d_in[1];
    const float* v  = (const float*)d_in[2];
    const float* Wq = (const float*)d_in[3];
    const float* bq = (const float*)d_in[4];
    const float* Wk = (const float*)d_in[5];
    const float* bk = (const float*)d_in[6];
    const float* Wv = (const float*)d_in[7];
    const float* bv = (const float*)d_in[8];
    float* out = (float*)d_out;

    const int psmem = (2 * 64 * XS + 2 * 64 * WS) * 4;             // 71680 B
    const int asmem = (2 * 64 * KSS + 2 * 64 * VSS + 64) * 4;      // 71936 B
    cudaFuncSetAttribute(proj_kernel, cudaFuncAttributeMaxDynamicSharedMemorySize, psmem);
    cudaFuncSetAttribute(attn_kernel, cudaFuncAttributeMaxDynamicSharedMemorySize, asmem);

    dim3 wgrid(32, 1, 3);
    wprep_kernel<<<wgrid, 256>>>(Wq, Wk, Wv);

    dim3 pgrid(BATCH * SEQ / 64, 1, 3);
    proj_kernel<<<pgrid, 256, psmem>>>(q, k, v, bq, bk, bv);

    dim3 agrid(SEQ / 64, BATCH);
    attn_kernel<<<agrid, 512, asmem>>>(out);
}

// round 13
// speedup vs baseline: 3.5642x; 1.0873x over previous
#include <cuda_runtime.h>
#include <cstdint>
#include <math.h>

#define BATCH  4
#define SEQ    2048
#define DMODEL 1024
#define DK     64

// Q/K: tf32 bits, Q pre-scaled 0.125, d-columns pair-permuted (j<4 -> 2j else 2(j-4)+1).
__device__ unsigned g_proj[2][BATCH * SEQ * DK];
// V: pair-packed rows (r, r+4): word = rp*128 + 2*((c + 4*(r&3))&63) + ((r>>2)&1),
//    rp = (r>>3)*4 + (r&3).   [BATCH*SEQ/2][128] words.
__device__ unsigned g_v2[(BATCH * SEQ / 2) * 128];
// W: pair-packed rows (k, k+4), same scheme. [3][512][128] words.
__device__ unsigned g_w2[3][512 * 128];

extern __shared__ unsigned dyn_smem[];

// ---- helpers ---------------------------------------------------------------
__device__ __forceinline__ unsigned f2tf(float x) {
    unsigned u;
    asm("cvt.rna.tf32.f32 %0, %1;" : "=r"(u) : "f"(x));
    return u;
}

__device__ __forceinline__ void mma8(float4& d,
                                     unsigned a0, unsigned a1, unsigned a2, unsigned a3,
                                     unsigned b0, unsigned b1) {
    asm("mma.sync.aligned.m16n8k8.row.col.f32.tf32.tf32.f32 "
        "{%0,%1,%2,%3},{%4,%5,%6,%7},{%8,%9},{%0,%1,%2,%3};"
        : "+f"(d.x), "+f"(d.y), "+f"(d.z), "+f"(d.w)
        : "r"(a0), "r"(a1), "r"(a2), "r"(a3), "r"(b0), "r"(b1));
}

__device__ __forceinline__ uint32_t smem_u32(const void* p) {
    return (uint32_t)__cvta_generic_to_shared(p);
}
__device__ __forceinline__ void cp_async16(uint32_t dst, const void* src) {
    asm volatile("cp.async.cg.shared.global [%0], [%1], 16;" :: "r"(dst), "l"(src) : "memory");
}
__device__ __forceinline__ void cp_commit() {
    asm volatile("cp.async.commit_group;" ::: "memory");
}
__device__ __forceinline__ void cp_wait0() {
    asm volatile("cp.async.wait_group 0;" ::: "memory");
}

// ===========================================================================
// wprep: W f32 [k][n] -> pair-packed tf32.  grid (64,1,3), 256 thr, 1 float4 ea.
// ===========================================================================
__global__ __launch_bounds__(256) void wprep_kernel(
    const float* __restrict__ w0, const float* __restrict__ w1, const float* __restrict__ w2)
{
    const int sel = blockIdx.z;
    const float* __restrict__ W = (sel == 0) ? w0 : (sel == 1) ? w1 : w2;
    unsigned* __restrict__ O = g_w2[sel];

    int idx4 = blockIdx.x * 256 + threadIdx.x;   // 0..16383
    int k  = idx4 >> 4;
    int n4 = (idx4 & 15) * 4;
    float4 wv = *(const float4*)(W + (size_t)k * DK + n4);
    int kp   = ((k >> 3) << 2) | (k & 3);
    int slot = (k >> 2) & 1;
    int rot  = 4 * (k & 3);
    unsigned v[4] = {f2tf(wv.x), f2tf(wv.y), f2tf(wv.z), f2tf(wv.w)};
#pragma unroll
    for (int j = 0; j < 4; ++j) {
        int colp = (n4 + j + rot) & 63;
        O[kp * 128 + 2 * colp + slot] = v[j];
    }
}

// ===========================================================================
// Projection: Y = tf32(X @ W + b); Q scaled 0.125; Q/K col-pair-permuted;
// V written pair-packed to g_v2.  grid (128,1,3), 256 thr, K chunks of 64.
// X: LDG -> cvt -> STS.  W: cp.async of pair-packed tiles (LDS.64 b-frags).
// ===========================================================================
#define XS 68   // Xs stride: a-frag bank = 4g+m, conflict-free

__global__ __launch_bounds__(256) void proj_kernel(
    const float* __restrict__ x0, const float* __restrict__ x1, const float* __restrict__ x2,
    const float* __restrict__ b0v, const float* __restrict__ b1v, const float* __restrict__ b2v)
{
    unsigned* Xs = dyn_smem;               // 2 * 64*68 = 8704 words
    unsigned* Ws = dyn_smem + 2 * 64 * XS; // 2 * 4096 = 8192 words (pair-packed tiles)
    const uint32_t ws_u32 = smem_u32(Ws);

    const int sel = blockIdx.z;
    const float* __restrict__ X  = (sel == 0) ? x0 : (sel == 1) ? x1 : x2;
    const float* __restrict__ Bb = (sel == 0) ? b0v : (sel == 1) ? b1v : b2v;
    const unsigned* __restrict__ Wt2 = g_w2[sel];
    const float oscale = (sel == 0) ? 0.125f : 1.0f;

    const int tid  = threadIdx.x;
    const int lane = tid & 31;
    const int g    = lane >> 2;
    const int m    = lane & 3;
    const int wid  = tid >> 5;
    const int wr   = wid & 3;      // row group (16 rows)
    const int wc   = wid >> 2;     // col group (32 cols)
    const int row0 = blockIdx.x * 64;

    const int lr = tid >> 4;
    const int lc = (tid & 15) * 4;

    float4 acc[4];
#pragma unroll
    for (int n = 0; n < 4; ++n) acc[n] = make_float4(0.f, 0.f, 0.f, 0.f);

    // ---- prefetch chunk 0 ----
    float4 xr[4];
#pragma unroll
    for (int p = 0; p < 4; ++p) {
        int r = lr + p * 16;
        xr[p] = *(const float4*)(X + (size_t)(row0 + r) * DMODEL + lc);
    }
#pragma unroll
    for (int p = 0; p < 4; ++p) {
        int idx = tid + p * 256;             // 0..1023 uint4 chunks
        cp_async16(ws_u32 + (uint32_t)(idx * 4) * 4, Wt2 + idx * 4);
    }
    cp_commit();
#pragma unroll
    for (int p = 0; p < 4; ++p) {
        int r = lr + p * 16;
        *(uint4*)&Xs[r * XS + lc] =
            make_uint4(f2tf(xr[p].x), f2tf(xr[p].y), f2tf(xr[p].z), f2tf(xr[p].w));
    }
    cp_wait0();
    __syncthreads();

    const int cb = 32 * wc + g + 4 * m;      // rotated base col for b-frags

    int cur = 0;
    for (int c = 0; c < 16; ++c) {
        const unsigned* Xc = Xs + cur * 64 * XS;
        const unsigned* Wc = Ws + cur * 4096;
        const int nxt = cur ^ 1;
        const bool has_next = (c + 1 < 16);

        if (has_next) {
            const int k0 = (c + 1) * 64;
#pragma unroll
            for (int p = 0; p < 4; ++p) {
                int r = lr + p * 16;
                xr[p] = *(const float4*)(X + (size_t)(row0 + r) * DMODEL + k0 + lc);
            }
#pragma unroll
            for (int p = 0; p < 4; ++p) {
                int idx = tid + p * 256;
                cp_async16(ws_u32 + (uint32_t)(nxt * 4096 + idx * 4) * 4,
                           Wt2 + (c + 1) * 4096 + idx * 4);
            }
            cp_commit();
        }

        // compute: 8 k-steps x 4 n-tiles; b-frags are single LDS.64
#pragma unroll
        for (int kk = 0; kk < 8; ++kk) {
            int r = 16 * wr + g;
            unsigned a0 = Xc[r * XS + kk * 8 + m];
            unsigned a1 = Xc[(r + 8) * XS + kk * 8 + m];
            unsigned a2 = Xc[r * XS + kk * 8 + m + 4];
            unsigned a3 = Xc[(r + 8) * XS + kk * 8 + m + 4];
            const unsigned* Wrow = Wc + (kk * 4 + m) * 128;
#pragma unroll
            for (int n = 0; n < 4; ++n) {
                int colp = (cb + 8 * n) & 63;
                uint2 wb = *(const uint2*)&Wrow[2 * colp];
                mma8(acc[n], a0, a1, a2, a3, wb.x, wb.y);
            }
        }

        if (has_next) {
            unsigned* Xn = Xs + nxt * 64 * XS;
#pragma unroll
            for (int p = 0; p < 4; ++p) {
                int r = lr + p * 16;
                *(uint4*)&Xn[r * XS + lc] =
                    make_uint4(f2tf(xr[p].x), f2tf(xr[p].y), f2tf(xr[p].z), f2tf(xr[p].w));
            }
        }
        cp_wait0();
        __syncthreads();
        cur = nxt;
    }

    // epilogue
#pragma unroll
    for (int n = 0; n < 4; ++n) {
        int col = 32 * wc + n * 8 + 2 * m;
        float bj0 = Bb[col];
        float bj1 = Bb[col + 1];
        int r = row0 + 16 * wr + g;
        unsigned o00 = f2tf((acc[n].x + bj0) * oscale);
        unsigned o01 = f2tf((acc[n].y + bj1) * oscale);
        unsigned o10 = f2tf((acc[n].z + bj0) * oscale);
        unsigned o11 = f2tf((acc[n].w + bj1) * oscale);
        if (sel == 2) {
            // pair-packed V scatter
#pragma unroll
            for (int e = 0; e < 4; ++e) {
                int R  = (e & 2) ? (r + 8) : r;
                int cc = col + (e & 1);
                unsigned val = (e == 0) ? o00 : (e == 1) ? o01 : (e == 2) ? o10 : o11;
                int rp   = ((R >> 3) << 2) | (R & 3);
                int slot = (R >> 2) & 1;
                int colp = (cc + 4 * (R & 3)) & 63;
                g_v2[rp * 128 + 2 * colp + slot] = val;
            }
        } else {
            unsigned* __restrict__ Y = g_proj[sel];
            int base = 32 * wc + n * 8;
            int pos0 = (m < 2) ? 4 * m : 4 * m - 7;   // col-pair permutation of j=2m
            Y[(size_t)r * DK + base + pos0]           = o00;
            Y[(size_t)r * DK + base + pos0 + 2]       = o01;
            Y[(size_t)(r + 8) * DK + base + pos0]     = o10;
            Y[(size_t)(r + 8) * DK + base + pos0 + 2] = o11;
        }
    }
}

// ===========================================================================
// Fused attention: Q/K col-pair-permuted tf32 bits; V pair-packed.
// cp.async K/V, double-buffered, 512 thr.  All MMA b-frags are LDS.64.
// ===========================================================================
#define KSS 68

__global__ __launch_bounds__(512, 1) void attn_kernel(float* __restrict__ out)
{
    unsigned* Ks = dyn_smem;                 // 2 * 64*68 = 8704 words
    unsigned* Vs = dyn_smem + 2 * 64 * KSS;  // 2 * 4096 = 8192 words (pair-packed)
    float* den = (float*)(dyn_smem + 2 * 64 * KSS + 2 * 4096);
    float* Of0 = (float*)Ks;                 // 4096 <= 8704
    float* Of1 = (float*)Vs;                 // 4096 <= 8192
    const uint32_t ks_u32 = smem_u32(Ks);
    const uint32_t vs_u32 = smem_u32(Vs);

    const int tid  = threadIdx.x;
    const int wid  = tid >> 5;
    const int lane = tid & 31;
    const int g    = lane >> 2;
    const int m    = lane & 3;
    const int wr   = wid & 3;
    const int wkc  = wid >> 2;

    const int b  = blockIdx.y;
    const int q0 = blockIdx.x * 64;

    const unsigned* __restrict__ Qg = g_proj[0] + ((size_t)b * SEQ + q0) * DK;
    const unsigned* __restrict__ Kg = g_proj[1] + (size_t)b * SEQ * DK;

    const int lr = tid >> 4;
    const int lc = (tid & 15) * 4;

    if (tid < 64) den[tid] = 0.f;

    // ---- stage Q through Ks buffer 0; a-frag pairs load as LDS.64 ----------
#pragma unroll
    for (int p = 0; p < 2; ++p) {
        int r = lr + p * 32;
        *(uint4*)&Ks[r * KSS + lc] = *(const uint4*)(Qg + (size_t)r * DK + lc);
    }
    __syncthreads();

    unsigned qa[8][4];
#pragma unroll
    for (int kk = 0; kk < 8; ++kk) {
        int r = 16 * wr + g;
        uint2 qlo = *(const uint2*)&Ks[r * KSS + kk * 8 + 2 * m];
        uint2 qhi = *(const uint2*)&Ks[(r + 8) * KSS + kk * 8 + 2 * m];
        qa[kk][0] = qlo.x;
        qa[kk][2] = qlo.y;
        qa[kk][1] = qhi.x;
        qa[kk][3] = qhi.y;
    }
    __syncthreads();

    float4 oacc[8];
#pragma unroll
    for (int n = 0; n < 8; ++n) {
        oacc[n] = make_float4(0.f, 0.f, 0.f, 0.f);
    }
    float dp0 = 0.f;
    float dp1 = 0.f;

    const int s0 = (lane & ~3) | (m >> 1);
    const int s1 = s0 + 2;
    const bool od = (m & 1);

    // ---- preload tile 0 ----
#pragma unroll
    for (int p = 0; p < 2; ++p) {
        int r = lr + p * 32;
        cp_async16(ks_u32 + (uint32_t)(r * KSS + lc) * 4, Kg + (size_t)r * DK + lc);
    }
    {
        const unsigned* Vsrc = g_v2 + ((size_t)b * (SEQ / 2)) * 128;
#pragma unroll
        for (int p = 0; p < 2; ++p) {
            int idx = tid + p * 512;            // 0..1023 uint4 chunks
            cp_async16(vs_u32 + (uint32_t)(idx * 4) * 4, Vsrc + idx * 4);
        }
    }
    cp_commit();

    const int vcb = g + 4 * m;   // rotated base col for V b-frags

    int cur = 0;
    for (int t = 0; t < SEQ / 64; ++t) {
        cp_wait0();
        __syncthreads();

        const unsigned* Kc = Ks + cur * 64 * KSS;
        const unsigned* Vc = Vs + cur * 4096;
        const int nxt = cur ^ 1;

        if (t + 1 < SEQ / 64) {
            int n1 = (t + 1) * 64;
#pragma unroll
            for (int p = 0; p < 2; ++p) {
                int r = lr + p * 32;
                cp_async16(ks_u32 + (uint32_t)(nxt * 64 * KSS + r * KSS + lc) * 4,
                           Kg + (size_t)(n1 + r) * DK + lc);
            }
            const unsigned* Vsrc = g_v2 + ((size_t)b * (SEQ / 2) + (size_t)(t + 1) * 32) * 128;
#pragma unroll
            for (int p = 0; p < 2; ++p) {
                int idx = tid + p * 512;
                cp_async16(vs_u32 + (uint32_t)(nxt * 4096 + idx * 4) * 4, Vsrc + idx * 4);
            }
            cp_commit();
        }

        // ---- S = Q K^T ----
        float4 sa[2];
        sa[0] = make_float4(0.f, 0.f, 0.f, 0.f);
        sa[1] = make_float4(0.f, 0.f, 0.f, 0.f);
#pragma unroll
        for (int kk = 0; kk < 8; ++kk) {
#pragma unroll
            for (int n = 0; n < 2; ++n) {
                int krow = 16 * wkc + n * 8 + g;
                uint2 kb = *(const uint2*)&Kc[krow * KSS + kk * 8 + 2 * m];
                mma8(sa[n], qa[kk][0], qa[kk][1], qa[kk][2], qa[kk][3], kb.x, kb.y);
            }
        }

        // ---- exp ----
#pragma unroll
        for (int n = 0; n < 2; ++n) {
            float e0 = __uint_as_float(f2tf(__expf(sa[n].x)));
            float e1 = __uint_as_float(f2tf(__expf(sa[n].y)));
            float e2 = __uint_as_float(f2tf(__expf(sa[n].z)));
            float e3 = __uint_as_float(f2tf(__expf(sa[n].w)));
            dp0 += e0 + e1;
            dp1 += e2 + e3;
            sa[n] = make_float4(e0, e1, e2, e3);
        }

        // ---- O += E V (pair-packed V: LDS.64 b-frags) ----
#pragma unroll
        for (int kk2 = 0; kk2 < 2; ++kk2) {
            float c0 = sa[kk2].x;
            float c1 = sa[kk2].y;
            float c2 = sa[kk2].z;
            float c3 = sa[kk2].w;
            float x00 = __shfl_sync(0xffffffffu, c0, s0);
            float x01 = __shfl_sync(0xffffffffu, c1, s0);
            float x10 = __shfl_sync(0xffffffffu, c2, s0);
            float x11 = __shfl_sync(0xffffffffu, c3, s0);
            float x20 = __shfl_sync(0xffffffffu, c0, s1);
            float x21 = __shfl_sync(0xffffffffu, c1, s1);
            float x30 = __shfl_sync(0xffffffffu, c2, s1);
            float x31 = __shfl_sync(0xffffffffu, c3, s1);
            unsigned a0 = __float_as_uint(od ? x01 : x00);
            unsigned a1 = __float_as_uint(od ? x11 : x10);
            unsigned a2 = __float_as_uint(od ? x21 : x20);
            unsigned a3 = __float_as_uint(od ? x31 : x30);
            const unsigned* Vrow = Vc + ((2 * wkc + kk2) * 4 + m) * 128;
#pragma unroll
            for (int n2 = 0; n2 < 8; ++n2) {
                int colp = (vcb + 8 * n2) & 63;
                uint2 vb = *(const uint2*)&Vrow[2 * colp];
                mma8(oacc[n2], a0, a1, a2, a3, vb.x, vb.y);
            }
        }

        cur = nxt;
    }
    __syncthreads();

    // ---- denominator ----
    dp0 += __shfl_xor_sync(0xffffffffu, dp0, 1);
    dp0 += __shfl_xor_sync(0xffffffffu, dp0, 2);
    dp1 += __shfl_xor_sync(0xffffffffu, dp1, 1);
    dp1 += __shfl_xor_sync(0xffffffffu, dp1, 2);
    if (m == 0) {
        atomicAdd(&den[16 * wr + g], dp0);
        atomicAdd(&den[16 * wr + g + 8], dp1);
    }

    // ---- O reduction ----
    if (wkc == 0) {
#pragma unroll
        for (int n2 = 0; n2 < 8; ++n2) {
            int r = 16 * wr + g;
            int col = n2 * 8 + 2 * m;
            *(float2*)&Of0[r * 64 + col]       = make_float2(oacc[n2].x, oacc[n2].y);
            *(float2*)&Of0[(r + 8) * 64 + col] = make_float2(oacc[n2].z, oacc[n2].w);
        }
    } else if (wkc == 1) {
#pragma unroll
        for (int n2 = 0; n2 < 8; ++n2) {
            int r = 16 * wr + g;
            int col = n2 * 8 + 2 * m;
            *(float2*)&Of1[r * 64 + col]       = make_float2(oacc[n2].x, oacc[n2].y);
            *(float2*)&Of1[(r + 8) * 64 + col] = make_float2(oacc[n2].z, oacc[n2].w);
        }
    }
    __syncthreads();
    if (wkc == 2) {
#pragma unroll
        for (int n2 = 0; n2 < 8; ++n2) {
            int r = 16 * wr + g;
            int col = n2 * 8 + 2 * m;
            float2 p0 = *(float2*)&Of0[r * 64 + col];
            float2 p1 = *(float2*)&Of0[(r + 8) * 64 + col];
            p0.x += oacc[n2].x; p0.y += oacc[n2].y;
            p1.x += oacc[n2].z; p1.y += oacc[n2].w;
            *(float2*)&Of0[r * 64 + col]       = p0;
            *(float2*)&Of0[(r + 8) * 64 + col] = p1;
        }
    } else if (wkc == 3) {
#pragma unroll
        for (int n2 = 0; n2 < 8; ++n2) {
            int r = 16 * wr + g;
            int col = n2 * 8 + 2 * m;
            float2 p0 = *(float2*)&Of1[r * 64 + col];
            float2 p1 = *(float2*)&Of1[(r + 8) * 64 + col];
            p0.x += oacc[n2].x; p0.y += oacc[n2].y;
            p1.x += oacc[n2].z; p1.y += oacc[n2].w;
            *(float2*)&Of1[r * 64 + col]       = p0;
            *(float2*)&Of1[(r + 8) * 64 + col] = p1;
        }
    }
    __syncthreads();

    // ---- normalize + writeout ----
    float* __restrict__ Og = out + ((size_t)b * SEQ + q0) * DK;
#pragma unroll
    for (int i = 0; i < 2; ++i) {
        int e4 = tid + i * 512;
        int row = e4 >> 4;
        float inv = 1.0f / den[row];
        float4 oa = ((const float4*)Of0)[e4];
        float4 ob = ((const float4*)Of1)[e4];
        float4 o;
        o.x = (oa.x + ob.x) * inv;
        o.y = (oa.y + ob.y) * inv;
        o.z = (oa.z + ob.z) * inv;
        o.w = (oa.w + ob.w) * inv;
        ((float4*)Og)[e4] = o;
    }
}

// ---------------------------------------------------------------------------
extern "C" void kernel_launch(void* const* d_in, const int* in_sizes, int n_in,
                              void* d_out, int out_size)
{
    const float* q  = (const float*)d_in[0];
    const float* k  = (const float*)d_in[1];
    const float* v  = (const float*)d_in[2];
    const float* Wq = (const float*)d_in[3];
    const float* bq = (const float*)d_in[4];
    const float* Wk = (const float*)d_in[5];
    const float* bk = (const float*)d_in[6];
    const float* Wv = (const float*)d_in[7];
    const float* bv = (const float*)d_in[8];
    float* out = (float*)d_out;

    const int psmem = (2 * 64 * XS + 2 * 4096) * 4;            // 67584 B
    const int asmem = (2 * 64 * KSS + 2 * 4096 + 64) * 4;      // 67840 B
    cudaFuncSetAttribute(proj_kernel, cudaFuncAttributeMaxDynamicSharedMemorySize, psmem);
    cudaFuncSetAttribute(attn_kernel, cudaFuncAttributeMaxDynamicSharedMemorySize, asmem);

    dim3 wgrid(64, 1, 3);
    wprep_kernel<<<wgrid, 256>>>(Wq, Wk, Wv);

    dim3 pgrid(BATCH * SEQ / 64, 1, 3);
    proj_kernel<<<pgrid, 256, psmem>>>(q, k, v, bq, bk, bv);

    dim3 agrid(SEQ / 64, BATCH);
    attn_kernel<<<agrid, 512, asmem>>>(out);
}